// round 9
// baseline (speedup 1.0000x reference)
#include <cuda_runtime.h>
#include <cuda_fp16.h>
#include <cstdint>

#define BB 16
#define QL 16
#define DD 256
#define NH 4
#define HD 64
#define PLEN 512
#define GLEN 16384
#define MAXS 32
#define GM (BB * GLEN)      // 262144
#define PM (BB * PLEN)      // 8192
#define SSTR 132

// ------------------------- scratch (device globals) -------------------------
__device__ __half g_kh_g[(size_t)GM * DD];
__device__ __half g_kl_g[(size_t)GM * DD];
__device__ __half g_vh_g[(size_t)GM * DD];
__device__ __half g_kh_p[PM * DD];
__device__ __half g_kl_p[PM * DD];
__device__ __half g_vh_p[PM * DD];
__device__ __half g_wkv_h[2][512 * DD];
__device__ __half g_wkv_l[2][512 * DD];
__device__ float g_mem[2][BB * QL * DD];
__device__ float g_hq[BB * QL * DD];
__device__ float g_vec[BB * QL * DD];
__device__ float g_ao[BB * QL * DD];
__device__ float g_pacc[BB * NH * MAXS * QL * HD];
__device__ float g_pm[BB * NH * MAXS * QL];
__device__ float g_pl[BB * NH * MAXS * QL];

// ------------------------- fast exp on FMA pipe -----------------------------
__device__ __forceinline__ float fexp(float x) {
    float y = x * 1.4426950408889634f;
    y = fmaxf(y, -125.0f);
    float n = rintf(y);
    float f = y - n;
    float p = 1.3333558146e-3f;
    p = fmaf(p, f, 9.6181291076e-3f);
    p = fmaf(p, f, 5.5504108664e-2f);
    p = fmaf(p, f, 2.4022650696e-1f);
    p = fmaf(p, f, 6.9314718056e-1f);
    p = fmaf(p, f, 1.0f);
    return __int_as_float(((int)n + 127) << 23) * p;
}

// ------------------------- mma / smem / cp.async helpers --------------------
__device__ __forceinline__ uint32_t smem_u32(const void* p) {
    uint32_t a;
    asm("{ .reg .u64 t; cvta.to.shared.u64 t, %1; cvt.u32.u64 %0, t; }" : "=r"(a) : "l"(p));
    return a;
}
__device__ __forceinline__ void ldm_x4(uint32_t* r, uint32_t addr) {
    asm volatile("ldmatrix.sync.aligned.m8n8.x4.shared.b16 {%0,%1,%2,%3}, [%4];"
                 : "=r"(r[0]), "=r"(r[1]), "=r"(r[2]), "=r"(r[3]) : "r"(addr));
}
__device__ __forceinline__ void ldm_x4_t(uint32_t* r, uint32_t addr) {
    asm volatile("ldmatrix.sync.aligned.m8n8.x4.trans.shared.b16 {%0,%1,%2,%3}, [%4];"
                 : "=r"(r[0]), "=r"(r[1]), "=r"(r[2]), "=r"(r[3]) : "r"(addr));
}
__device__ __forceinline__ void mma16(float* c, const uint32_t* a, const uint32_t* b) {
    asm volatile(
        "mma.sync.aligned.m16n8k16.row.col.f32.f16.f16.f32 "
        "{%0,%1,%2,%3}, {%4,%5,%6,%7}, {%8,%9}, {%0,%1,%2,%3};"
        : "+f"(c[0]), "+f"(c[1]), "+f"(c[2]), "+f"(c[3])
        : "r"(a[0]), "r"(a[1]), "r"(a[2]), "r"(a[3]), "r"(b[0]), "r"(b[1]));
}
__device__ __forceinline__ void cp_a16(uint32_t s, const void* g) {
    asm volatile("cp.async.cg.shared.global [%0], [%1], 16;" :: "r"(s), "l"(g));
}
#define CP_COMMIT() asm volatile("cp.async.commit_group;" ::: "memory")
#define CP_WAIT0()  asm volatile("cp.async.wait_group 0;" ::: "memory")
#define CP_WAIT1()  asm volatile("cp.async.wait_group 1;" ::: "memory")

__device__ __forceinline__ void split2(float a, float b, uint32_t& hi, uint32_t& lo) {
    __half ha = __float2half_rn(a), hb = __float2half_rn(b);
    __half2 H = __halves2half2(ha, hb);
    hi = *(uint32_t*)&H;
    __half ra = __float2half_rn(a - __half2float(ha));
    __half rb = __float2half_rn(b - __half2float(hb));
    __half2 L = __halves2half2(ra, rb);
    lo = *(uint32_t*)&L;
}

// ------------------------- weight split (transposed, concat K|V) ------------
__global__ void __launch_bounds__(256) split_wkv(const float* __restrict__ Wk,
                                                 const float* __restrict__ Wv,
                                                 __half* __restrict__ Th,
                                                 __half* __restrict__ Tl) {
    int n = blockIdx.x, k = threadIdx.x;
    const float* W = (n < 256) ? Wk : Wv;
    float v = W[(size_t)k * DD + (n & 255)];
    __half h = __float2half_rn(v);
    Th[(size_t)n * DD + k] = h;
    Tl[(size_t)n * DD + k] = __float2half_rn(v - __half2float(h));
}

// ---------------- mma GEMM v3: [K|V](M,512) = X_fp32(M,256) @ Wt^T ----------
// 128 threads, warp tile 64x64, 2-stage cp.async/reg-prefetch pipeline.
#define CHB 10240           // one plane stage: 128 rows * 40 halves * 2B
#define GSTG (3 * CHB)      // stage stride (A, Bh, Bl)
#define KV_SMEM (2 * GSTG)  // 61440

__global__ void __launch_bounds__(128) gemm_kv(
    const float* __restrict__ X,
    const __half* __restrict__ Bhp, const __half* __restrict__ Blp,
    __half* __restrict__ Kh, __half* __restrict__ Kl,
    __half* __restrict__ Vh) {
    extern __shared__ char smk[];
    uint32_t uA = smem_u32(smk);

    int t = threadIdx.x;
    int wid = t >> 5, lane = t & 31;
    int wm = (wid & 1) * 64;
    int wn = (wid >> 1) * 64;
    size_t m0 = (size_t)blockIdx.y * 128;
    int n0 = blockIdx.x * 128;
    int q = lane >> 3, r8 = lane & 7;

    float acc[4][8][4];
#pragma unroll
    for (int i = 0; i < 4; i++)
#pragma unroll
        for (int j = 0; j < 8; j++)
#pragma unroll
            for (int e = 0; e < 4; e++) acc[i][j][e] = 0.f;

    // ---- prologue: chunk 0 into stage 0 ----
#pragma unroll
    for (int u = 0; u < 8; u++) {
        int f = t + 128 * u;
        int row = f >> 3, cc = f & 7;
        float4 v = *(const float4*)(X + (m0 + row) * DD + cc * 4);
        __half2 h0 = __floats2half2_rn(v.x, v.y);
        __half2 h1 = __floats2half2_rn(v.z, v.w);
        *(uint2*)(smk + row * 80 + cc * 8) =
            make_uint2(*(uint32_t*)&h0, *(uint32_t*)&h1);
    }
#pragma unroll
    for (int u = 0; u < 4; u++) {
        int f = t + 128 * u;
        int row = f >> 2, cc = f & 3;
        cp_a16(uA + CHB + row * 80 + cc * 16, Bhp + (size_t)(n0 + row) * DD + cc * 8);
        cp_a16(uA + 2 * CHB + row * 80 + cc * 16, Blp + (size_t)(n0 + row) * DD + cc * 8);
    }
    CP_COMMIT();
    CP_WAIT0();
    __syncthreads();

    for (int c = 0; c < 8; c++) {
        uint32_t cur = uA + (c & 1) * GSTG;
        bool has = (c + 1 < 8);
        uint2 pk[8];
        if (has) {
            int k0n = (c + 1) * 32;
#pragma unroll
            for (int u = 0; u < 8; u++) {
                int f = t + 128 * u;
                int row = f >> 3, cc = f & 7;
                float4 v = *(const float4*)(X + (m0 + row) * DD + k0n + cc * 4);
                __half2 h0 = __floats2half2_rn(v.x, v.y);
                __half2 h1 = __floats2half2_rn(v.z, v.w);
                pk[u] = make_uint2(*(uint32_t*)&h0, *(uint32_t*)&h1);
            }
            uint32_t nxt = uA + ((c + 1) & 1) * GSTG;
#pragma unroll
            for (int u = 0; u < 4; u++) {
                int f = t + 128 * u;
                int row = f >> 2, cc = f & 3;
                cp_a16(nxt + CHB + row * 80 + cc * 16,
                       Bhp + (size_t)(n0 + row) * DD + k0n + cc * 8);
                cp_a16(nxt + 2 * CHB + row * 80 + cc * 16,
                       Blp + (size_t)(n0 + row) * DD + k0n + cc * 8);
            }
            CP_COMMIT();
        }

        // ---- MMAs on current chunk ----
#pragma unroll
        for (int s = 0; s < 2; s++) {
            int kk = s * 16;
            uint32_t aH[4][4], bH[8][2], bL[8][2];
#pragma unroll
            for (int i = 0; i < 4; i++) {
                int row = wm + i * 16 + (q & 1) * 8 + r8;
                int col = kk + (q >> 1) * 8;
                ldm_x4(aH[i], cur + (uint32_t)(row * 40 + col) * 2);
            }
#pragma unroll
            for (int p = 0; p < 4; p++) {
                int n = wn + p * 16 + (q >> 1) * 8 + r8;
                int col = kk + (q & 1) * 8;
                uint32_t off = (uint32_t)(n * 40 + col) * 2;
                uint32_t rh[4], rl[4];
                ldm_x4(rh, cur + CHB + off);
                ldm_x4(rl, cur + 2 * CHB + off);
                bH[2 * p][0] = rh[0]; bH[2 * p][1] = rh[1];
                bH[2 * p + 1][0] = rh[2]; bH[2 * p + 1][1] = rh[3];
                bL[2 * p][0] = rl[0]; bL[2 * p][1] = rl[1];
                bL[2 * p + 1][0] = rl[2]; bL[2 * p + 1][1] = rl[3];
            }
#pragma unroll
            for (int i = 0; i < 4; i++)
#pragma unroll
                for (int j = 0; j < 8; j++) {
                    mma16(acc[i][j], aH[i], bH[j]);
                    mma16(acc[i][j], aH[i], bL[j]);
                }
        }

        if (has) {
            char* nxp = smk + ((c + 1) & 1) * GSTG;
#pragma unroll
            for (int u = 0; u < 8; u++) {
                int f = t + 128 * u;
                int row = f >> 3, cc = f & 7;
                *(uint2*)(nxp + row * 80 + cc * 8) = pk[u];
            }
            CP_WAIT0();
        }
        __syncthreads();
    }

    // ---- epilogue: split fp32 accum -> K hi/lo or V fp16 ----
    bool isK = (n0 < 256);
    int cbase = isK ? n0 : (n0 - 256);
#pragma unroll
    for (int i = 0; i < 4; i++) {
        int r0 = wm + i * 16 + (lane >> 2);
#pragma unroll
        for (int j = 0; j < 8; j++) {
            int cc = cbase + wn + j * 8 + (lane & 3) * 2;
            if (isK) {
                uint32_t hi, lo;
                split2(acc[i][j][0], acc[i][j][1], hi, lo);
                *(uint32_t*)(Kh + (m0 + r0) * DD + cc) = hi;
                *(uint32_t*)(Kl + (m0 + r0) * DD + cc) = lo;
                split2(acc[i][j][2], acc[i][j][3], hi, lo);
                *(uint32_t*)(Kh + (m0 + r0 + 8) * DD + cc) = hi;
                *(uint32_t*)(Kl + (m0 + r0 + 8) * DD + cc) = lo;
            } else {
                __half2 p0 = __floats2half2_rn(acc[i][j][0], acc[i][j][1]);
                __half2 p1 = __floats2half2_rn(acc[i][j][2], acc[i][j][3]);
                *(uint32_t*)(Vh + (m0 + r0) * DD + cc) = *(uint32_t*)&p0;
                *(uint32_t*)(Vh + (m0 + r0 + 8) * DD + cc) = *(uint32_t*)&p1;
            }
        }
    }
}

// ------------------------- mean pooling: graph -> mem0 ----------------------
__global__ void __launch_bounds__(256) pool_kernel(const float* __restrict__ graph,
                                                   float* __restrict__ mem0) {
    int bm = blockIdx.x;
    int d = threadIdx.x;
    const float* src = graph + (size_t)bm * 1024 * DD + d;
    float s0 = 0.f, s1 = 0.f, s2 = 0.f, s3 = 0.f;
    for (int r = 0; r < 1024; r += 4) {
        s0 += src[(size_t)(r + 0) * DD];
        s1 += src[(size_t)(r + 1) * DD];
        s2 += src[(size_t)(r + 2) * DD];
        s3 += src[(size_t)(r + 3) * DD];
    }
    mem0[(size_t)bm * DD + d] = (s0 + s1 + s2 + s3) * (1.0f / 1024.0f);
}

// ---------------- small GEMM: O[256,256] = X @ W, grid (16,16) --------------
__global__ void __launch_bounds__(256) gemm_small(const float* __restrict__ X,
                                                  const float* __restrict__ W,
                                                  float* __restrict__ O) {
    __shared__ float Xs[16][256];
    int t = threadIdx.x;
    int r0 = blockIdx.y * 16, n0 = blockIdx.x * 16;
#pragma unroll
    for (int u = 0; u < 4; u++) {
        int f = t + 256 * u;
        int row = f >> 6, c4 = (f & 63) << 2;
        *(float4*)&Xs[row][c4] = *(const float4*)(X + (size_t)(r0 + row) * DD + c4);
    }
    __syncthreads();
    int col = n0 + (t & 15), lr = t >> 4;
    float a0 = 0.f, a1 = 0.f, a2 = 0.f, a3 = 0.f;
#pragma unroll 8
    for (int k = 0; k < 256; k += 4) {
        a0 = fmaf(Xs[lr][k + 0], W[(size_t)(k + 0) * DD + col], a0);
        a1 = fmaf(Xs[lr][k + 1], W[(size_t)(k + 1) * DD + col], a1);
        a2 = fmaf(Xs[lr][k + 2], W[(size_t)(k + 2) * DD + col], a2);
        a3 = fmaf(Xs[lr][k + 3], W[(size_t)(k + 3) * DD + col], a3);
    }
    O[(size_t)(r0 + lr) * DD + col] = (a0 + a1) + (a2 + a3);
}

// ------ tensor-core flash attention v4: cp.async 2-stage pipeline -----------
#define ATT4_SMEM 107456
#define STAGE_BYTES 49152

__global__ void __launch_bounds__(256) attn_tc4(
    const float* __restrict__ hq,
    const __half* __restrict__ Kh, const __half* __restrict__ Kl,
    const __half* __restrict__ Vh,
    const int* __restrict__ mask, int klen, int kps) {
    extern __shared__ char sm[];
    float* Sst = (float*)(sm + 98304);
    float* rowM = (float*)(sm + 106752);
    float* rowL = (float*)(sm + 106816);
    float* rowS = (float*)(sm + 106880);
    int* mk = (int*)(sm + 106944);
    uint32_t uBase = smem_u32(sm);

    int t = threadIdx.x;
    int w = t >> 5, lane = t & 31;
    int g = lane >> 2, tig = lane & 3;
    int q2 = lane >> 3, r8 = lane & 7;
    int split = blockIdx.x, h = blockIdx.y, b = blockIdx.z;
    int key0 = split * kps;
    int ntiles = kps >> 7;

    {
        int r = t >> 4, c4 = (t & 15) << 2;
        *(float4*)&Sst[r * 64 + c4] =
            *(const float4*)(hq + (size_t)(b * QL + r) * DD + h * HD + c4);
    }
    if (t < 16) { rowM[t] = -3e38f; rowL[t] = 0.f; rowS[t] = 0.f; }
    __syncthreads();

#define LOAD_TILE(k0_, stg_) do {                                               \
    _Pragma("unroll")                                                           \
    for (int pl_ = 0; pl_ < 3; pl_++) {                                         \
        const __half* Gp_ = (pl_ == 0) ? Kh : ((pl_ == 1) ? Kl : Vh);           \
        uint32_t sb_ = (stg_) + pl_ * 16384;                                    \
        _Pragma("unroll")                                                       \
        for (int u_ = 0; u_ < 4; u_++) {                                        \
            int f_ = t + 256 * u_;                                              \
            int row_ = f_ >> 3, ch_ = f_ & 7;                                   \
            const char* gp_ = (const char*)(Gp_ +                               \
                ((size_t)b * klen + (k0_) + row_) * DD + h * HD) + ch_ * 16;    \
            uint32_t sa_ = sb_ + row_ * 128 + (((ch_ ^ (row_ & 7))) << 4);      \
            cp_a16(sa_, gp_);                                                   \
        }                                                                       \
    }                                                                           \
} while (0)

    LOAD_TILE(key0, uBase);
    CP_COMMIT();

    uint32_t qh[4][4], ql[4][4];
#pragma unroll
    for (int s = 0; s < 4; s++) {
        int cb = s * 16 + tig * 2;
        split2(Sst[g * 64 + cb], Sst[g * 64 + cb + 1], qh[s][0], ql[s][0]);
        split2(Sst[(g + 8) * 64 + cb], Sst[(g + 8) * 64 + cb + 1], qh[s][1], ql[s][1]);
        split2(Sst[g * 64 + cb + 8], Sst[g * 64 + cb + 9], qh[s][2], ql[s][2]);
        split2(Sst[(g + 8) * 64 + cb + 8], Sst[(g + 8) * 64 + cb + 9], qh[s][3], ql[s][3]);
    }

    float acc[4] = {0.f, 0.f, 0.f, 0.f};
    uint32_t* SW = (uint32_t*)Sst;

    for (int kt = 0; kt < ntiles; kt++) {
        uint32_t stage = uBase + (kt & 1) * STAGE_BYTES;
        int k0 = key0 + (kt << 7);
        __syncthreads();
        if (kt + 1 < ntiles) {
            LOAD_TILE(k0 + 128, uBase + ((kt + 1) & 1) * STAGE_BYTES);
            CP_COMMIT();
            CP_WAIT1();
        } else {
            CP_WAIT0();
        }
        __syncthreads();
        if (t < 128) mk[t] = mask[(size_t)b * klen + k0 + t];

        float c2[2][4];
#pragma unroll
        for (int j = 0; j < 2; j++)
#pragma unroll
            for (int e = 0; e < 4; e++) c2[j][e] = 0.f;
#pragma unroll
        for (int s = 0; s < 4; s++) {
            int row = w * 16 + (q2 >> 1) * 8 + r8;
            int ch = s * 2 + (q2 & 1);
            uint32_t off = stage + row * 128 + ((ch ^ (row & 7)) << 4);
            uint32_t rh[4], rl[4];
            ldm_x4(rh, off);
            ldm_x4(rl, off + 16384);
            uint32_t b0h[2] = {rh[0], rh[1]}, b1h[2] = {rh[2], rh[3]};
            uint32_t b0l[2] = {rl[0], rl[1]}, b1l[2] = {rl[2], rl[3]};
            mma16(c2[0], qh[s], b0h); mma16(c2[0], qh[s], b0l); mma16(c2[0], ql[s], b0h);
            mma16(c2[1], qh[s], b1h); mma16(c2[1], qh[s], b1l); mma16(c2[1], ql[s], b1h);
        }
#pragma unroll
        for (int j = 0; j < 2; j++) {
            int kc = w * 16 + j * 8 + tig * 2;
            Sst[g * SSTR + kc] = c2[j][0] * 0.125f;
            Sst[g * SSTR + kc + 1] = c2[j][1] * 0.125f;
            Sst[(g + 8) * SSTR + kc] = c2[j][2] * 0.125f;
            Sst[(g + 8) * SSTR + kc + 1] = c2[j][3] * 0.125f;
        }
        __syncthreads();

        {
            int row = t >> 4, sub = t & 15;
            int cb = sub * 8;
            float sv[8];
#pragma unroll
            for (int i = 0; i < 8; i++) sv[i] = Sst[row * SSTR + cb + i];
            float lmax = -3e38f;
#pragma unroll
            for (int i = 0; i < 8; i++)
                if (mk[cb + i]) lmax = fmaxf(lmax, sv[i]);
#pragma unroll
            for (int o = 8; o; o >>= 1) lmax = fmaxf(lmax, __shfl_xor_sync(~0u, lmax, o));
            float oldm = rowM[row];
            float newm = fmaxf(oldm, lmax);
            float pv[8];
            float lsum = 0.f;
#pragma unroll
            for (int i = 0; i < 8; i++) {
                pv[i] = mk[cb + i] ? fexp(sv[i] - newm) : 0.f;
                lsum += pv[i];
            }
#pragma unroll
            for (int o = 8; o; o >>= 1) lsum += __shfl_xor_sync(~0u, lsum, o);
            if (sub == 0) {
                float sc = fexp(oldm - newm);
                rowS[row] = sc;
                rowL[row] = rowL[row] * sc + lsum;
                rowM[row] = newm;
            }
#pragma unroll
            for (int i = 0; i < 8; i += 2) {
                uint32_t hi, lo;
                split2(pv[i], pv[i + 1], hi, lo);
                SW[row * SSTR + cb + i] = hi;
                SW[row * SSTR + cb + i + 1] = lo;
            }
        }
        __syncthreads();

        {
            float s0 = rowS[g], s1 = rowS[g + 8];
            acc[0] *= s0; acc[1] *= s0; acc[2] *= s1; acc[3] *= s1;
#pragma unroll
            for (int kb = 0; kb < 4; kb++) {
                int vrow = kb * 32 + q2 * 8 + r8;
                uint32_t voff = stage + 32768 + vrow * 128 + ((w ^ (vrow & 7)) << 4);
                uint32_t v4[4];
                ldm_x4_t(v4, voff);
#pragma unroll
                for (int kh2 = 0; kh2 < 2; kh2++) {
                    int kk = kb * 32 + kh2 * 16;
                    uint32_t ah[4] = {SW[g * SSTR + kk + tig * 2],
                                      SW[(g + 8) * SSTR + kk + tig * 2],
                                      SW[g * SSTR + kk + 8 + tig * 2],
                                      SW[(g + 8) * SSTR + kk + 8 + tig * 2]};
                    uint32_t al[4] = {SW[g * SSTR + kk + tig * 2 + 1],
                                      SW[(g + 8) * SSTR + kk + tig * 2 + 1],
                                      SW[g * SSTR + kk + 8 + tig * 2 + 1],
                                      SW[(g + 8) * SSTR + kk + 8 + tig * 2 + 1]};
                    uint32_t bh[2] = {v4[2 * kh2], v4[2 * kh2 + 1]};
                    mma16(acc, ah, bh);
                    mma16(acc, al, bh);
                }
            }
        }
    }
    size_t pbase = ((size_t)(b * NH + h) * MAXS + split) * QL;
    float* pa = g_pacc + pbase * HD;
    int cc = w * 8 + tig * 2;
    *(float2*)(pa + (size_t)g * HD + cc) = make_float2(acc[0], acc[1]);
    *(float2*)(pa + (size_t)(g + 8) * HD + cc) = make_float2(acc[2], acc[3]);
    if (t < 16) { g_pm[pbase + t] = rowM[t]; g_pl[pbase + t] = rowL[t]; }
}

// ------------------------- merge split-K partials ---------------------------
__global__ void __launch_bounds__(256) attn_merge(float* __restrict__ vec, int nsplit) {
    __shared__ float w[MAXS][16];
    __shared__ float invL[16];
    int t = threadIdx.x;
    int h = blockIdx.x, b = blockIdx.y;
    size_t base = (size_t)(b * NH + h) * MAXS * QL;
    if (t < 16) {
        float M = -3e38f;
        for (int s = 0; s < nsplit; s++) M = fmaxf(M, g_pm[base + s * QL + t]);
        float L = 0.f;
        for (int s = 0; s < nsplit; s++) {
            float ww = fexp(g_pm[base + s * QL + t] - M);
            w[s][t] = ww;
            L += g_pl[base + s * QL + t] * ww;
        }
        invL[t] = 1.f / L;
    }
    __syncthreads();
    int r = t >> 4, c4 = (t & 15) << 2;
    float ox = 0.f, oy = 0.f, oz = 0.f, ow = 0.f;
    for (int s = 0; s < nsplit; s++) {
        float ww = w[s][r];
        float4 a = *(const float4*)(g_pacc + (base + s * QL + r) * HD + c4);
        ox = fmaf(a.x, ww, ox); oy = fmaf(a.y, ww, oy);
        oz = fmaf(a.z, ww, oz); ow = fmaf(a.w, ww, ow);
    }
    float il = invL[r];
    *(float4*)(vec + (size_t)(b * QL + r) * DD + h * HD + c4) =
        make_float4(ox * il, oy * il, oz * il, ow * il);
}

// ------------------------- gate + residual ----------------------------------
__global__ void __launch_bounds__(256) gate_kernel(
    const float* __restrict__ mem, const float* __restrict__ ao,
    const float* __restrict__ Wg, const float* __restrict__ bg,
    float* __restrict__ out) {
    __shared__ float xs[512];
    int row = blockIdx.x;
    int c = threadIdx.x;
    xs[c] = mem[(size_t)row * DD + c];
    xs[256 + c] = ao[(size_t)row * DD + c];
    __syncthreads();
    float s0 = 0.f, s1 = 0.f, s2 = 0.f, s3 = 0.f;
#pragma unroll 4
    for (int k = 0; k < 512; k += 4) {
        float4 x = *(float4*)&xs[k];
        s0 = fmaf(x.x, Wg[(size_t)(k + 0) * DD + c], s0);
        s1 = fmaf(x.y, Wg[(size_t)(k + 1) * DD + c], s1);
        s2 = fmaf(x.z, Wg[(size_t)(k + 2) * DD + c], s2);
        s3 = fmaf(x.w, Wg[(size_t)(k + 3) * DD + c], s3);
    }
    float sum = (s0 + s1) + (s2 + s3) + bg[c];
    float gate = 1.f / (1.f + fexp(-sum));
    out[(size_t)row * DD + c] = gate * xs[c] + (1.f - gate) * xs[256 + c];
}

// ------------------------- launch -------------------------------------------
extern "C" void kernel_launch(void* const* d_in, const int* in_sizes, int n_in,
                              void* d_out, int out_size) {
    const float* pattern = (const float*)d_in[0];
    const float* graph = (const float*)d_in[1];
    const int* pmask = (const int*)d_in[2];
    const int* gmask = (const int*)d_in[3];
    const float* pW[6];
    const float* gW[6];
    for (int i = 0; i < 6; i++) pW[i] = (const float*)d_in[4 + i];
    for (int i = 0; i < 6; i++) gW[i] = (const float*)d_in[10 + i];
    float* out = (float*)d_out;

    float *memb, *hq, *vec, *ao;
    __half *khg, *klg, *vhg, *khp, *klp, *vhp, *wh, *wl;
    cudaGetSymbolAddress((void**)&memb, g_mem);
    cudaGetSymbolAddress((void**)&hq, g_hq);
    cudaGetSymbolAddress((void**)&vec, g_vec);
    cudaGetSymbolAddress((void**)&ao, g_ao);
    cudaGetSymbolAddress((void**)&khg, g_kh_g);
    cudaGetSymbolAddress((void**)&klg, g_kl_g);
    cudaGetSymbolAddress((void**)&vhg, g_vh_g);
    cudaGetSymbolAddress((void**)&khp, g_kh_p);
    cudaGetSymbolAddress((void**)&klp, g_kl_p);
    cudaGetSymbolAddress((void**)&vhp, g_vh_p);
    cudaGetSymbolAddress((void**)&wh, g_wkv_h);
    cudaGetSymbolAddress((void**)&wl, g_wkv_l);
    float* mem0 = memb;
    float* mem1 = memb + BB * QL * DD;

    cudaFuncSetAttribute(attn_tc4, cudaFuncAttributeMaxDynamicSharedMemorySize,
                         ATT4_SMEM);
    cudaFuncSetAttribute(gemm_kv, cudaFuncAttributeMaxDynamicSharedMemorySize,
                         KV_SMEM);

    // 4th launch gets profiled -> graph gemm_kv
    pool_kernel<<<256, 256>>>(graph, mem0);                               // 1
    split_wkv<<<512, 256>>>(gW[1], gW[2], wh + 512 * DD, wl + 512 * DD);  // 2
    split_wkv<<<512, 256>>>(pW[1], pW[2], wh, wl);                        // 3
    gemm_kv<<<dim3(4, GM / 128), 128, KV_SMEM>>>(graph, wh + 512 * DD,
                                                 wl + 512 * DD, khg, klg, vhg); // 4
    gemm_kv<<<dim3(4, PM / 128), 128, KV_SMEM>>>(pattern, wh, wl, khp, klp, vhp);

    float* cur = mem0;
    float* other = mem1;
    for (int it = 0; it < 3; it++) {
        for (int ph = 0; ph < 2; ph++) {
            const float* const* W = ph ? gW : pW;
            const __half* kh = ph ? khg : khp;
            const __half* kl = ph ? klg : klp;
            const __half* vh = ph ? vhg : vhp;
            const int* mask = ph ? gmask : pmask;
            int klen = ph ? GLEN : PLEN;
            int splits = ph ? 16 : 4;
            int kps = klen / splits;

            gemm_small<<<dim3(16, 16), 256>>>(cur, W[0], hq);
            attn_tc4<<<dim3(splits, NH, BB), 256, ATT4_SMEM>>>(hq, kh, kl, vh,
                                                               mask, klen, kps);
            attn_merge<<<dim3(NH, BB), 256>>>(vec, splits);
            gemm_small<<<dim3(16, 16), 256>>>(vec, W[3], ao);

            bool last = (it == 2 && ph == 1);
            float* dst = last ? out : other;
            gate_kernel<<<256, 256>>>(cur, ao, W[4], W[5], dst);
            other = cur;
            cur = dst;
        }
    }
}

// round 10
// speedup vs baseline: 1.1232x; 1.1232x over previous
#include <cuda_runtime.h>
#include <cuda_fp16.h>
#include <cstdint>

#define BB 16
#define QL 16
#define DD 256
#define NH 4
#define HD 64
#define PLEN 512
#define GLEN 16384
#define MAXS 32
#define GM (BB * GLEN)      // 262144
#define PM (BB * PLEN)      // 8192
#define SSTR 132

// ------------------------- scratch (device globals) -------------------------
__device__ __half g_kh_g[(size_t)GM * DD];
__device__ __half g_kl_g[(size_t)GM * DD];
__device__ __half g_vh_g[(size_t)GM * DD];
__device__ __half g_kh_p[PM * DD];
__device__ __half g_kl_p[PM * DD];
__device__ __half g_vh_p[PM * DD];
__device__ __half g_wkv_h[2][512 * DD];
__device__ float g_mem[2][BB * QL * DD];
__device__ float g_hq[BB * QL * DD];
__device__ float g_vec[BB * QL * DD];
__device__ float g_ao[BB * QL * DD];
__device__ float g_pacc[BB * NH * MAXS * QL * HD];
__device__ float g_pm[BB * NH * MAXS * QL];
__device__ float g_pl[BB * NH * MAXS * QL];

// ------------------------- fast exp on FMA pipe -----------------------------
__device__ __forceinline__ float fexp(float x) {
    float y = x * 1.4426950408889634f;
    y = fmaxf(y, -125.0f);
    float n = rintf(y);
    float f = y - n;
    float p = 1.3333558146e-3f;
    p = fmaf(p, f, 9.6181291076e-3f);
    p = fmaf(p, f, 5.5504108664e-2f);
    p = fmaf(p, f, 2.4022650696e-1f);
    p = fmaf(p, f, 6.9314718056e-1f);
    p = fmaf(p, f, 1.0f);
    return __int_as_float(((int)n + 127) << 23) * p;
}

// ------------------------- mma / smem / cp.async helpers --------------------
__device__ __forceinline__ uint32_t smem_u32(const void* p) {
    uint32_t a;
    asm("{ .reg .u64 t; cvta.to.shared.u64 t, %1; cvt.u32.u64 %0, t; }" : "=r"(a) : "l"(p));
    return a;
}
__device__ __forceinline__ void ldm_x4(uint32_t* r, uint32_t addr) {
    asm volatile("ldmatrix.sync.aligned.m8n8.x4.shared.b16 {%0,%1,%2,%3}, [%4];"
                 : "=r"(r[0]), "=r"(r[1]), "=r"(r[2]), "=r"(r[3]) : "r"(addr));
}
__device__ __forceinline__ void ldm_x4_t(uint32_t* r, uint32_t addr) {
    asm volatile("ldmatrix.sync.aligned.m8n8.x4.trans.shared.b16 {%0,%1,%2,%3}, [%4];"
                 : "=r"(r[0]), "=r"(r[1]), "=r"(r[2]), "=r"(r[3]) : "r"(addr));
}
__device__ __forceinline__ void mma16(float* c, const uint32_t* a, const uint32_t* b) {
    asm volatile(
        "mma.sync.aligned.m16n8k16.row.col.f32.f16.f16.f32 "
        "{%0,%1,%2,%3}, {%4,%5,%6,%7}, {%8,%9}, {%0,%1,%2,%3};"
        : "+f"(c[0]), "+f"(c[1]), "+f"(c[2]), "+f"(c[3])
        : "r"(a[0]), "r"(a[1]), "r"(a[2]), "r"(a[3]), "r"(b[0]), "r"(b[1]));
}
__device__ __forceinline__ void cp_a16(uint32_t s, const void* g) {
    asm volatile("cp.async.cg.shared.global [%0], [%1], 16;" :: "r"(s), "l"(g));
}
#define CP_COMMIT() asm volatile("cp.async.commit_group;" ::: "memory")
#define CP_WAIT0()  asm volatile("cp.async.wait_group 0;" ::: "memory")
#define CP_WAIT1()  asm volatile("cp.async.wait_group 1;" ::: "memory")

__device__ __forceinline__ void split2(float a, float b, uint32_t& hi, uint32_t& lo) {
    __half ha = __float2half_rn(a), hb = __float2half_rn(b);
    __half2 H = __halves2half2(ha, hb);
    hi = *(uint32_t*)&H;
    __half ra = __float2half_rn(a - __half2float(ha));
    __half rb = __float2half_rn(b - __half2float(hb));
    __half2 L = __halves2half2(ra, rb);
    lo = *(uint32_t*)&L;
}

// ------------------------- weight convert (transposed, concat K|V) ----------
__global__ void __launch_bounds__(256) split_wkv(const float* __restrict__ Wk,
                                                 const float* __restrict__ Wv,
                                                 __half* __restrict__ Th) {
    int n = blockIdx.x, k = threadIdx.x;
    const float* W = (n < 256) ? Wk : Wv;
    Th[(size_t)n * DD + k] = __float2half_rn(W[(size_t)k * DD + (n & 255)]);
}

// ---------------- mma GEMM: [K|V](M,512) = X_fp32(M,256) @ Wt^T -------------
// 1-pass fp16 (xh*wh); X converted fp32 -> fp16 in-register while staging.
#define APAD 40

__global__ void __launch_bounds__(256) gemm_kv(
    const float* __restrict__ X,
    const __half* __restrict__ Bhp,
    __half* __restrict__ Kh, __half* __restrict__ Kl,
    __half* __restrict__ Vh) {
    __shared__ __half Ah[128 * APAD];
    __shared__ __half Bh[128 * APAD];

    int t = threadIdx.x;
    int wid = t >> 5, lane = t & 31;
    int wm = (wid & 3) * 32;
    int wn = (wid >> 2) * 64;
    size_t m0 = (size_t)blockIdx.y * 128;
    int n0 = blockIdx.x * 128;

    uint32_t sAh = smem_u32(Ah);
    uint32_t sBh = smem_u32(Bh);

    float acc[2][8][4];
#pragma unroll
    for (int i = 0; i < 2; i++)
#pragma unroll
        for (int j = 0; j < 8; j++)
#pragma unroll
            for (int e = 0; e < 4; e++) acc[i][j][e] = 0.f;

    for (int k0 = 0; k0 < 256; k0 += 32) {
        __syncthreads();
        // A: load fp32, convert to fp16, store 8B chunks
#pragma unroll
        for (int u = 0; u < 4; u++) {
            int f = t + 256 * u;              // 0..1023
            int row = f >> 3, c = f & 7;
            float4 v = *(const float4*)(X + (m0 + row) * DD + k0 + c * 4);
            __half2 h0 = __floats2half2_rn(v.x, v.y);
            __half2 h1 = __floats2half2_rn(v.z, v.w);
            *(uint2*)((char*)Ah + row * (APAD * 2) + c * 8) =
                make_uint2(*(uint32_t*)&h0, *(uint32_t*)&h1);
        }
        // B: single fp16 plane (16B chunks)
#pragma unroll
        for (int u = 0; u < 2; u++) {
            int f = t + 256 * u;              // 0..511
            int row = f >> 2, c = f & 3;
            *(uint4*)((char*)Bh + row * (APAD * 2) + c * 16) =
                *((const uint4*)(Bhp + (size_t)(n0 + row) * DD + k0) + c);
        }
        __syncthreads();

#pragma unroll
        for (int s = 0; s < 2; s++) {
            int kk = s * 16;
            uint32_t aH[2][4], bH[8][2];
#pragma unroll
            for (int i = 0; i < 2; i++) {
                int q = lane >> 3, r8 = lane & 7;
                int row = wm + i * 16 + (q & 1) * 8 + r8;
                int col = kk + (q >> 1) * 8;
                ldm_x4(aH[i], sAh + (uint32_t)(row * APAD + col) * 2);
            }
#pragma unroll
            for (int p = 0; p < 4; p++) {
                int q = lane >> 3, r8 = lane & 7;
                int n = wn + p * 16 + (q >> 1) * 8 + r8;
                int col = kk + (q & 1) * 8;
                uint32_t rh[4];
                ldm_x4(rh, sBh + (uint32_t)(n * APAD + col) * 2);
                bH[2 * p][0] = rh[0]; bH[2 * p][1] = rh[1];
                bH[2 * p + 1][0] = rh[2]; bH[2 * p + 1][1] = rh[3];
            }
#pragma unroll
            for (int i = 0; i < 2; i++)
#pragma unroll
                for (int j = 0; j < 8; j++)
                    mma16(acc[i][j], aH[i], bH[j]);
        }
    }
    bool isK = (n0 < 256);
    int cbase = isK ? n0 : (n0 - 256);
#pragma unroll
    for (int i = 0; i < 2; i++) {
        int r0 = wm + i * 16 + (lane >> 2);
#pragma unroll
        for (int j = 0; j < 8; j++) {
            int c = cbase + wn + j * 8 + (lane & 3) * 2;
            if (isK) {
                uint32_t hi, lo;
                split2(acc[i][j][0], acc[i][j][1], hi, lo);
                *(uint32_t*)(Kh + (m0 + r0) * DD + c) = hi;
                *(uint32_t*)(Kl + (m0 + r0) * DD + c) = lo;
                split2(acc[i][j][2], acc[i][j][3], hi, lo);
                *(uint32_t*)(Kh + (m0 + r0 + 8) * DD + c) = hi;
                *(uint32_t*)(Kl + (m0 + r0 + 8) * DD + c) = lo;
            } else {
                __half2 p0 = __floats2half2_rn(acc[i][j][0], acc[i][j][1]);
                __half2 p1 = __floats2half2_rn(acc[i][j][2], acc[i][j][3]);
                *(uint32_t*)(Vh + (m0 + r0) * DD + c) = *(uint32_t*)&p0;
                *(uint32_t*)(Vh + (m0 + r0 + 8) * DD + c) = *(uint32_t*)&p1;
            }
        }
    }
}

// ------------------------- mean pooling: graph -> mem0 ----------------------
__global__ void __launch_bounds__(256) pool_kernel(const float* __restrict__ graph,
                                                   float* __restrict__ mem0) {
    int bm = blockIdx.x;
    int d = threadIdx.x;
    const float* src = graph + (size_t)bm * 1024 * DD + d;
    float s0 = 0.f, s1 = 0.f, s2 = 0.f, s3 = 0.f;
    for (int r = 0; r < 1024; r += 4) {
        s0 += src[(size_t)(r + 0) * DD];
        s1 += src[(size_t)(r + 1) * DD];
        s2 += src[(size_t)(r + 2) * DD];
        s3 += src[(size_t)(r + 3) * DD];
    }
    mem0[(size_t)bm * DD + d] = (s0 + s1 + s2 + s3) * (1.0f / 1024.0f);
}

// ---------------- small GEMM: O[256,256] = X @ W, grid (16,16) --------------
__global__ void __launch_bounds__(256) gemm_small(const float* __restrict__ X,
                                                  const float* __restrict__ W,
                                                  float* __restrict__ O) {
    __shared__ float Xs[16][256];
    int t = threadIdx.x;
    int r0 = blockIdx.y * 16, n0 = blockIdx.x * 16;
#pragma unroll
    for (int u = 0; u < 4; u++) {
        int f = t + 256 * u;
        int row = f >> 6, c4 = (f & 63) << 2;
        *(float4*)&Xs[row][c4] = *(const float4*)(X + (size_t)(r0 + row) * DD + c4);
    }
    __syncthreads();
    int col = n0 + (t & 15), lr = t >> 4;
    float a0 = 0.f, a1 = 0.f, a2 = 0.f, a3 = 0.f;
#pragma unroll 8
    for (int k = 0; k < 256; k += 4) {
        a0 = fmaf(Xs[lr][k + 0], W[(size_t)(k + 0) * DD + col], a0);
        a1 = fmaf(Xs[lr][k + 1], W[(size_t)(k + 1) * DD + col], a1);
        a2 = fmaf(Xs[lr][k + 2], W[(size_t)(k + 2) * DD + col], a2);
        a3 = fmaf(Xs[lr][k + 3], W[(size_t)(k + 3) * DD + col], a3);
    }
    O[(size_t)(r0 + lr) * DD + col] = (a0 + a1) + (a2 + a3);
}

// ------ tensor-core flash attention v4: cp.async 2-stage pipeline -----------
#define ATT4_SMEM 107456
#define STAGE_BYTES 49152

__global__ void __launch_bounds__(256) attn_tc4(
    const float* __restrict__ hq,
    const __half* __restrict__ Kh, const __half* __restrict__ Kl,
    const __half* __restrict__ Vh,
    const int* __restrict__ mask, int klen, int kps) {
    extern __shared__ char sm[];
    float* Sst = (float*)(sm + 98304);
    float* rowM = (float*)(sm + 106752);
    float* rowL = (float*)(sm + 106816);
    float* rowS = (float*)(sm + 106880);
    int* mk = (int*)(sm + 106944);
    uint32_t uBase = smem_u32(sm);

    int t = threadIdx.x;
    int w = t >> 5, lane = t & 31;
    int g = lane >> 2, tig = lane & 3;
    int q2 = lane >> 3, r8 = lane & 7;
    int split = blockIdx.x, h = blockIdx.y, b = blockIdx.z;
    int key0 = split * kps;
    int ntiles = kps >> 7;

    {
        int r = t >> 4, c4 = (t & 15) << 2;
        *(float4*)&Sst[r * 64 + c4] =
            *(const float4*)(hq + (size_t)(b * QL + r) * DD + h * HD + c4);
    }
    if (t < 16) { rowM[t] = -3e38f; rowL[t] = 0.f; rowS[t] = 0.f; }
    __syncthreads();

#define LOAD_TILE(k0_, stg_) do {                                               \
    _Pragma("unroll")                                                           \
    for (int pl_ = 0; pl_ < 3; pl_++) {                                         \
        const __half* Gp_ = (pl_ == 0) ? Kh : ((pl_ == 1) ? Kl : Vh);           \
        uint32_t sb_ = (stg_) + pl_ * 16384;                                    \
        _Pragma("unroll")                                                       \
        for (int u_ = 0; u_ < 4; u_++) {                                        \
            int f_ = t + 256 * u_;                                              \
            int row_ = f_ >> 3, ch_ = f_ & 7;                                   \
            const char* gp_ = (const char*)(Gp_ +                               \
                ((size_t)b * klen + (k0_) + row_) * DD + h * HD) + ch_ * 16;    \
            uint32_t sa_ = sb_ + row_ * 128 + (((ch_ ^ (row_ & 7))) << 4);      \
            cp_a16(sa_, gp_);                                                   \
        }                                                                       \
    }                                                                           \
} while (0)

    LOAD_TILE(key0, uBase);
    CP_COMMIT();

    uint32_t qh[4][4], ql[4][4];
#pragma unroll
    for (int s = 0; s < 4; s++) {
        int cb = s * 16 + tig * 2;
        split2(Sst[g * 64 + cb], Sst[g * 64 + cb + 1], qh[s][0], ql[s][0]);
        split2(Sst[(g + 8) * 64 + cb], Sst[(g + 8) * 64 + cb + 1], qh[s][1], ql[s][1]);
        split2(Sst[g * 64 + cb + 8], Sst[g * 64 + cb + 9], qh[s][2], ql[s][2]);
        split2(Sst[(g + 8) * 64 + cb + 8], Sst[(g + 8) * 64 + cb + 9], qh[s][3], ql[s][3]);
    }

    float acc[4] = {0.f, 0.f, 0.f, 0.f};
    uint32_t* SW = (uint32_t*)Sst;

    for (int kt = 0; kt < ntiles; kt++) {
        uint32_t stage = uBase + (kt & 1) * STAGE_BYTES;
        int k0 = key0 + (kt << 7);
        __syncthreads();
        if (kt + 1 < ntiles) {
            LOAD_TILE(k0 + 128, uBase + ((kt + 1) & 1) * STAGE_BYTES);
            CP_COMMIT();
            CP_WAIT1();
        } else {
            CP_WAIT0();
        }
        __syncthreads();
        if (t < 128) mk[t] = mask[(size_t)b * klen + k0 + t];

        float c2[2][4];
#pragma unroll
        for (int j = 0; j < 2; j++)
#pragma unroll
            for (int e = 0; e < 4; e++) c2[j][e] = 0.f;
#pragma unroll
        for (int s = 0; s < 4; s++) {
            int row = w * 16 + (q2 >> 1) * 8 + r8;
            int ch = s * 2 + (q2 & 1);
            uint32_t off = stage + row * 128 + ((ch ^ (row & 7)) << 4);
            uint32_t rh[4], rl[4];
            ldm_x4(rh, off);
            ldm_x4(rl, off + 16384);
            uint32_t b0h[2] = {rh[0], rh[1]}, b1h[2] = {rh[2], rh[3]};
            uint32_t b0l[2] = {rl[0], rl[1]}, b1l[2] = {rl[2], rl[3]};
            mma16(c2[0], qh[s], b0h); mma16(c2[0], qh[s], b0l); mma16(c2[0], ql[s], b0h);
            mma16(c2[1], qh[s], b1h); mma16(c2[1], qh[s], b1l); mma16(c2[1], ql[s], b1h);
        }
#pragma unroll
        for (int j = 0; j < 2; j++) {
            int kc = w * 16 + j * 8 + tig * 2;
            Sst[g * SSTR + kc] = c2[j][0] * 0.125f;
            Sst[g * SSTR + kc + 1] = c2[j][1] * 0.125f;
            Sst[(g + 8) * SSTR + kc] = c2[j][2] * 0.125f;
            Sst[(g + 8) * SSTR + kc + 1] = c2[j][3] * 0.125f;
        }
        __syncthreads();

        {
            int row = t >> 4, sub = t & 15;
            int cb = sub * 8;
            float sv[8];
#pragma unroll
            for (int i = 0; i < 8; i++) sv[i] = Sst[row * SSTR + cb + i];
            float lmax = -3e38f;
#pragma unroll
            for (int i = 0; i < 8; i++)
                if (mk[cb + i]) lmax = fmaxf(lmax, sv[i]);
#pragma unroll
            for (int o = 8; o; o >>= 1) lmax = fmaxf(lmax, __shfl_xor_sync(~0u, lmax, o));
            float oldm = rowM[row];
            float newm = fmaxf(oldm, lmax);
            float pv[8];
            float lsum = 0.f;
#pragma unroll
            for (int i = 0; i < 8; i++) {
                pv[i] = mk[cb + i] ? fexp(sv[i] - newm) : 0.f;
                lsum += pv[i];
            }
#pragma unroll
            for (int o = 8; o; o >>= 1) lsum += __shfl_xor_sync(~0u, lsum, o);
            if (sub == 0) {
                float sc = fexp(oldm - newm);
                rowS[row] = sc;
                rowL[row] = rowL[row] * sc + lsum;
                rowM[row] = newm;
            }
#pragma unroll
            for (int i = 0; i < 8; i += 2) {
                uint32_t hi, lo;
                split2(pv[i], pv[i + 1], hi, lo);
                SW[row * SSTR + cb + i] = hi;
                SW[row * SSTR + cb + i + 1] = lo;
            }
        }
        __syncthreads();

        {
            float s0 = rowS[g], s1 = rowS[g + 8];
            acc[0] *= s0; acc[1] *= s0; acc[2] *= s1; acc[3] *= s1;
#pragma unroll
            for (int kb = 0; kb < 4; kb++) {
                int vrow = kb * 32 + q2 * 8 + r8;
                uint32_t voff = stage + 32768 + vrow * 128 + ((w ^ (vrow & 7)) << 4);
                uint32_t v4[4];
                ldm_x4_t(v4, voff);
#pragma unroll
                for (int kh2 = 0; kh2 < 2; kh2++) {
                    int kk = kb * 32 + kh2 * 16;
                    uint32_t ah[4] = {SW[g * SSTR + kk + tig * 2],
                                      SW[(g + 8) * SSTR + kk + tig * 2],
                                      SW[g * SSTR + kk + 8 + tig * 2],
                                      SW[(g + 8) * SSTR + kk + 8 + tig * 2]};
                    uint32_t al[4] = {SW[g * SSTR + kk + tig * 2 + 1],
                                      SW[(g + 8) * SSTR + kk + tig * 2 + 1],
                                      SW[g * SSTR + kk + 8 + tig * 2 + 1],
                                      SW[(g + 8) * SSTR + kk + 8 + tig * 2 + 1]};
                    uint32_t bh[2] = {v4[2 * kh2], v4[2 * kh2 + 1]};
                    mma16(acc, ah, bh);
                    mma16(acc, al, bh);
                }
            }
        }
    }
    size_t pbase = ((size_t)(b * NH + h) * MAXS + split) * QL;
    float* pa = g_pacc + pbase * HD;
    int cc = w * 8 + tig * 2;
    *(float2*)(pa + (size_t)g * HD + cc) = make_float2(acc[0], acc[1]);
    *(float2*)(pa + (size_t)(g + 8) * HD + cc) = make_float2(acc[2], acc[3]);
    if (t < 16) { g_pm[pbase + t] = rowM[t]; g_pl[pbase + t] = rowL[t]; }
}

// ------------------------- merge split-K partials ---------------------------
__global__ void __launch_bounds__(256) attn_merge(float* __restrict__ vec, int nsplit) {
    __shared__ float w[MAXS][16];
    __shared__ float invL[16];
    int t = threadIdx.x;
    int h = blockIdx.x, b = blockIdx.y;
    size_t base = (size_t)(b * NH + h) * MAXS * QL;
    if (t < 16) {
        float M = -3e38f;
        for (int s = 0; s < nsplit; s++) M = fmaxf(M, g_pm[base + s * QL + t]);
        float L = 0.f;
        for (int s = 0; s < nsplit; s++) {
            float ww = fexp(g_pm[base + s * QL + t] - M);
            w[s][t] = ww;
            L += g_pl[base + s * QL + t] * ww;
        }
        invL[t] = 1.f / L;
    }
    __syncthreads();
    int r = t >> 4, c4 = (t & 15) << 2;
    float ox = 0.f, oy = 0.f, oz = 0.f, ow = 0.f;
    for (int s = 0; s < nsplit; s++) {
        float ww = w[s][r];
        float4 a = *(const float4*)(g_pacc + (base + s * QL + r) * HD + c4);
        ox = fmaf(a.x, ww, ox); oy = fmaf(a.y, ww, oy);
        oz = fmaf(a.z, ww, oz); ow = fmaf(a.w, ww, ow);
    }
    float il = invL[r];
    *(float4*)(vec + (size_t)(b * QL + r) * DD + h * HD + c4) =
        make_float4(ox * il, oy * il, oz * il, ow * il);
}

// ------------------------- gate + residual ----------------------------------
__global__ void __launch_bounds__(256) gate_kernel(
    const float* __restrict__ mem, const float* __restrict__ ao,
    const float* __restrict__ Wg, const float* __restrict__ bg,
    float* __restrict__ out) {
    __shared__ float xs[512];
    int row = blockIdx.x;
    int c = threadIdx.x;
    xs[c] = mem[(size_t)row * DD + c];
    xs[256 + c] = ao[(size_t)row * DD + c];
    __syncthreads();
    float s0 = 0.f, s1 = 0.f, s2 = 0.f, s3 = 0.f;
#pragma unroll 4
    for (int k = 0; k < 512; k += 4) {
        float4 x = *(float4*)&xs[k];
        s0 = fmaf(x.x, Wg[(size_t)(k + 0) * DD + c], s0);
        s1 = fmaf(x.y, Wg[(size_t)(k + 1) * DD + c], s1);
        s2 = fmaf(x.z, Wg[(size_t)(k + 2) * DD + c], s2);
        s3 = fmaf(x.w, Wg[(size_t)(k + 3) * DD + c], s3);
    }
    float sum = (s0 + s1) + (s2 + s3) + bg[c];
    float gate = 1.f / (1.f + fexp(-sum));
    out[(size_t)row * DD + c] = gate * xs[c] + (1.f - gate) * xs[256 + c];
}

// ------------------------- launch -------------------------------------------
extern "C" void kernel_launch(void* const* d_in, const int* in_sizes, int n_in,
                              void* d_out, int out_size) {
    const float* pattern = (const float*)d_in[0];
    const float* graph = (const float*)d_in[1];
    const int* pmask = (const int*)d_in[2];
    const int* gmask = (const int*)d_in[3];
    const float* pW[6];
    const float* gW[6];
    for (int i = 0; i < 6; i++) pW[i] = (const float*)d_in[4 + i];
    for (int i = 0; i < 6; i++) gW[i] = (const float*)d_in[10 + i];
    float* out = (float*)d_out;

    float *memb, *hq, *vec, *ao;
    __half *khg, *klg, *vhg, *khp, *klp, *vhp, *wh;
    cudaGetSymbolAddress((void**)&memb, g_mem);
    cudaGetSymbolAddress((void**)&hq, g_hq);
    cudaGetSymbolAddress((void**)&vec, g_vec);
    cudaGetSymbolAddress((void**)&ao, g_ao);
    cudaGetSymbolAddress((void**)&khg, g_kh_g);
    cudaGetSymbolAddress((void**)&klg, g_kl_g);
    cudaGetSymbolAddress((void**)&vhg, g_vh_g);
    cudaGetSymbolAddress((void**)&khp, g_kh_p);
    cudaGetSymbolAddress((void**)&klp, g_kl_p);
    cudaGetSymbolAddress((void**)&vhp, g_vh_p);
    cudaGetSymbolAddress((void**)&wh, g_wkv_h);
    float* mem0 = memb;
    float* mem1 = memb + BB * QL * DD;

    cudaFuncSetAttribute(attn_tc4, cudaFuncAttributeMaxDynamicSharedMemorySize,
                         ATT4_SMEM);

    // 4th launch gets profiled -> graph gemm_kv
    pool_kernel<<<256, 256>>>(graph, mem0);                               // 1
    split_wkv<<<512, 256>>>(gW[1], gW[2], wh + 512 * DD);                 // 2
    split_wkv<<<512, 256>>>(pW[1], pW[2], wh);                            // 3
    gemm_kv<<<dim3(4, GM / 128), 256>>>(graph, wh + 512 * DD, khg, klg, vhg); // 4
    gemm_kv<<<dim3(4, PM / 128), 256>>>(pattern, wh, khp, klp, vhp);      // 5

    float* cur = mem0;
    float* other = mem1;
    for (int it = 0; it < 3; it++) {
        for (int ph = 0; ph < 2; ph++) {
            const float* const* W = ph ? gW : pW;
            const __half* kh = ph ? khg : khp;
            const __half* kl = ph ? klg : klp;
            const __half* vh = ph ? vhg : vhp;
            const int* mask = ph ? gmask : pmask;
            int klen = ph ? GLEN : PLEN;
            int splits = ph ? 16 : 4;
            int kps = klen / splits;

            gemm_small<<<dim3(16, 16), 256>>>(cur, W[0], hq);
            attn_tc4<<<dim3(splits, NH, BB), 256, ATT4_SMEM>>>(hq, kh, kl, vh,
                                                               mask, klen, kps);
            attn_merge<<<dim3(NH, BB), 256>>>(vec, splits);
            gemm_small<<<dim3(16, 16), 256>>>(vec, W[3], ao);

            bool last = (it == 2 && ph == 1);
            float* dst = last ? out : other;
            gate_kernel<<<256, 256>>>(cur, ao, W[4], W[5], dst);
            other = cur;
            cur = dst;
        }
    }
}

// round 11
// speedup vs baseline: 1.3660x; 1.2162x over previous
#include <cuda_runtime.h>
#include <cuda_fp16.h>
#include <cstdint>

#define BB 16
#define QL 16
#define DD 256
#define NH 4
#define HD 64
#define PLEN 512
#define GLEN 16384
#define MAXS 32
#define GM (BB * GLEN)      // 262144
#define PM (BB * PLEN)      // 8192
#define SSTR 132

// ------------------------- scratch (device globals) -------------------------
__device__ __half g_kh_g[(size_t)GM * DD];
__device__ __half g_vh_g[(size_t)GM * DD];
__device__ __half g_kh_p[PM * DD];
__device__ __half g_vh_p[PM * DD];
__device__ __half g_wkv_h[2][512 * DD];
__device__ float g_mem[2][BB * QL * DD];
__device__ float g_hq[BB * QL * DD];
__device__ float g_vec[BB * QL * DD];
__device__ float g_ao[BB * QL * DD];
__device__ float g_pacc[BB * NH * MAXS * QL * HD];
__device__ float g_pm[BB * NH * MAXS * QL];
__device__ float g_pl[BB * NH * MAXS * QL];

// ------------------------- fast exp on FMA pipe -----------------------------
__device__ __forceinline__ float fexp(float x) {
    float y = x * 1.4426950408889634f;
    y = fmaxf(y, -125.0f);
    float n = rintf(y);
    float f = y - n;
    float p = 1.3333558146e-3f;
    p = fmaf(p, f, 9.6181291076e-3f);
    p = fmaf(p, f, 5.5504108664e-2f);
    p = fmaf(p, f, 2.4022650696e-1f);
    p = fmaf(p, f, 6.9314718056e-1f);
    p = fmaf(p, f, 1.0f);
    return __int_as_float(((int)n + 127) << 23) * p;
}

// ------------------------- mma / smem / cp.async helpers --------------------
__device__ __forceinline__ uint32_t smem_u32(const void* p) {
    uint32_t a;
    asm("{ .reg .u64 t; cvta.to.shared.u64 t, %1; cvt.u32.u64 %0, t; }" : "=r"(a) : "l"(p));
    return a;
}
__device__ __forceinline__ void ldm_x4(uint32_t* r, uint32_t addr) {
    asm volatile("ldmatrix.sync.aligned.m8n8.x4.shared.b16 {%0,%1,%2,%3}, [%4];"
                 : "=r"(r[0]), "=r"(r[1]), "=r"(r[2]), "=r"(r[3]) : "r"(addr));
}
__device__ __forceinline__ void ldm_x4_t(uint32_t* r, uint32_t addr) {
    asm volatile("ldmatrix.sync.aligned.m8n8.x4.trans.shared.b16 {%0,%1,%2,%3}, [%4];"
                 : "=r"(r[0]), "=r"(r[1]), "=r"(r[2]), "=r"(r[3]) : "r"(addr));
}
__device__ __forceinline__ void mma16(float* c, const uint32_t* a, const uint32_t* b) {
    asm volatile(
        "mma.sync.aligned.m16n8k16.row.col.f32.f16.f16.f32 "
        "{%0,%1,%2,%3}, {%4,%5,%6,%7}, {%8,%9}, {%0,%1,%2,%3};"
        : "+f"(c[0]), "+f"(c[1]), "+f"(c[2]), "+f"(c[3])
        : "r"(a[0]), "r"(a[1]), "r"(a[2]), "r"(a[3]), "r"(b[0]), "r"(b[1]));
}
__device__ __forceinline__ void cp_a16(uint32_t s, const void* g) {
    asm volatile("cp.async.cg.shared.global [%0], [%1], 16;" :: "r"(s), "l"(g));
}
#define CP_COMMIT() asm volatile("cp.async.commit_group;" ::: "memory")
#define CP_WAIT0()  asm volatile("cp.async.wait_group 0;" ::: "memory")
#define CP_WAIT1()  asm volatile("cp.async.wait_group 1;" ::: "memory")

__device__ __forceinline__ void split2(float a, float b, uint32_t& hi, uint32_t& lo) {
    __half ha = __float2half_rn(a), hb = __float2half_rn(b);
    __half2 H = __halves2half2(ha, hb);
    hi = *(uint32_t*)&H;
    __half ra = __float2half_rn(a - __half2float(ha));
    __half rb = __float2half_rn(b - __half2float(hb));
    __half2 L = __halves2half2(ra, rb);
    lo = *(uint32_t*)&L;
}

// ------------------------- weight convert (transposed, concat K|V) ----------
__global__ void __launch_bounds__(256) split_wkv(const float* __restrict__ Wk,
                                                 const float* __restrict__ Wv,
                                                 __half* __restrict__ Th) {
    int n = blockIdx.x, k = threadIdx.x;
    const float* W = (n < 256) ? Wk : Wv;
    Th[(size_t)n * DD + k] = __float2half_rn(W[(size_t)k * DD + (n & 255)]);
}

// ------- mma GEMM v4: A-panel resident, N-loop in block, cp.async B ---------
// grid (M/128), 256 threads. A 128x256 fp16 swizzled (64KB) + B 2x10.2KB.
#define A_BYTES 65536
#define BSTG 10240
#define KV_SMEM (A_BYTES + 2 * BSTG)   // 86016

__global__ void __launch_bounds__(256) gemm_kv(
    const float* __restrict__ X, const __half* __restrict__ Bhp,
    __half* __restrict__ Kh, __half* __restrict__ Vh) {
    extern __shared__ char smk[];
    uint32_t uA = smem_u32(smk);
    uint32_t uB = uA + A_BYTES;

    int t = threadIdx.x;
    int wid = t >> 5, lane = t & 31;
    int wm = (wid & 3) * 32;
    int wn = (wid >> 2) * 64;
    size_t m0 = (size_t)blockIdx.x * 128;
    int q = lane >> 3, r8 = lane & 7;

    // ---- load & convert full A panel (fp32 -> fp16, XOR-swizzled rows) ----
#pragma unroll 8
    for (int u = 0; u < 32; u++) {
        int f = t + 256 * u;               // 0..8191
        int row = f >> 6, c = f & 63;      // c = float4 index in row
        float4 v = *(const float4*)(X + (m0 + row) * DD + c * 4);
        __half2 h0 = __floats2half2_rn(v.x, v.y);
        __half2 h1 = __floats2half2_rn(v.z, v.w);
        uint32_t off = row * 512 + (((c >> 1) ^ (row & 7)) << 4) + (c & 1) * 8;
        *(uint2*)(smk + off) = make_uint2(*(uint32_t*)&h0, *(uint32_t*)&h1);
    }
    __syncthreads();

    for (int nb = 0; nb < 4; nb++) {
        int n0 = nb * 128;
        float acc[2][8][4];
#pragma unroll
        for (int i = 0; i < 2; i++)
#pragma unroll
            for (int j = 0; j < 8; j++)
#pragma unroll
                for (int e = 0; e < 4; e++) acc[i][j][e] = 0.f;

        // B prologue: chunk 0 -> stage 0
#pragma unroll
        for (int u = 0; u < 2; u++) {
            int f = t + 256 * u;
            int row = f >> 2, c = f & 3;
            cp_a16(uB + row * 80 + c * 16,
                   Bhp + (size_t)(n0 + row) * DD + c * 8);
        }
        CP_COMMIT();

        for (int c = 0; c < 8; c++) {
            uint32_t curB = uB + (c & 1) * BSTG;
            __syncthreads();               // alt stage free (prev-prev consumed)
            if (c + 1 < 8) {
                int k0n = (c + 1) * 32;
                uint32_t nxtB = uB + ((c + 1) & 1) * BSTG;
#pragma unroll
                for (int u = 0; u < 2; u++) {
                    int f = t + 256 * u;
                    int row = f >> 2, cc = f & 3;
                    cp_a16(nxtB + row * 80 + cc * 16,
                           Bhp + (size_t)(n0 + row) * DD + k0n + cc * 8);
                }
                CP_COMMIT();
                CP_WAIT1();
            } else {
                CP_WAIT0();
            }
            __syncthreads();

            int k0 = c * 32;
#pragma unroll
            for (int s = 0; s < 2; s++) {
                int kk = k0 + s * 16;
                uint32_t aH[2][4], bH[8][2];
#pragma unroll
                for (int i = 0; i < 2; i++) {
                    int row = wm + i * 16 + (q & 1) * 8 + r8;
                    int col = kk + (q >> 1) * 8;
                    uint32_t off = row * 512 + ((((uint32_t)col >> 3) ^ (row & 7)) << 4);
                    ldm_x4(aH[i], uA + off);
                }
#pragma unroll
                for (int p = 0; p < 4; p++) {
                    int n = wn + p * 16 + (q >> 1) * 8 + r8;
                    int col = s * 16 + (q & 1) * 8;
                    uint32_t rh[4];
                    ldm_x4(rh, curB + (uint32_t)(n * 40 + col) * 2);
                    bH[2 * p][0] = rh[0]; bH[2 * p][1] = rh[1];
                    bH[2 * p + 1][0] = rh[2]; bH[2 * p + 1][1] = rh[3];
                }
#pragma unroll
                for (int i = 0; i < 2; i++)
#pragma unroll
                    for (int j = 0; j < 8; j++)
                        mma16(acc[i][j], aH[i], bH[j]);
            }
        }

        // epilogue: single fp16 plane for both K and V
        __half* Dst = (n0 < 256) ? Kh : Vh;
        int cbase = n0 & 255;
#pragma unroll
        for (int i = 0; i < 2; i++) {
            int r0 = wm + i * 16 + (lane >> 2);
#pragma unroll
            for (int j = 0; j < 8; j++) {
                int cc = cbase + wn + j * 8 + (lane & 3) * 2;
                __half2 p0 = __floats2half2_rn(acc[i][j][0], acc[i][j][1]);
                __half2 p1 = __floats2half2_rn(acc[i][j][2], acc[i][j][3]);
                *(uint32_t*)(Dst + (m0 + r0) * DD + cc) = *(uint32_t*)&p0;
                *(uint32_t*)(Dst + (m0 + r0 + 8) * DD + cc) = *(uint32_t*)&p1;
            }
        }
    }
}

// ------------------------- mean pooling: graph -> mem0 ----------------------
__global__ void __launch_bounds__(256) pool_kernel(const float* __restrict__ graph,
                                                   float* __restrict__ mem0) {
    int bm = blockIdx.x;
    int d = threadIdx.x;
    const float* src = graph + (size_t)bm * 1024 * DD + d;
    float s0 = 0.f, s1 = 0.f, s2 = 0.f, s3 = 0.f;
    for (int r = 0; r < 1024; r += 4) {
        s0 += src[(size_t)(r + 0) * DD];
        s1 += src[(size_t)(r + 1) * DD];
        s2 += src[(size_t)(r + 2) * DD];
        s3 += src[(size_t)(r + 3) * DD];
    }
    mem0[(size_t)bm * DD + d] = (s0 + s1 + s2 + s3) * (1.0f / 1024.0f);
}

// ---------------- small GEMM: O[256,256] = X @ W, grid (16,16) --------------
__global__ void __launch_bounds__(256) gemm_small(const float* __restrict__ X,
                                                  const float* __restrict__ W,
                                                  float* __restrict__ O) {
    __shared__ float Xs[16][256];
    int t = threadIdx.x;
    int r0 = blockIdx.y * 16, n0 = blockIdx.x * 16;
#pragma unroll
    for (int u = 0; u < 4; u++) {
        int f = t + 256 * u;
        int row = f >> 6, c4 = (f & 63) << 2;
        *(float4*)&Xs[row][c4] = *(const float4*)(X + (size_t)(r0 + row) * DD + c4);
    }
    __syncthreads();
    int col = n0 + (t & 15), lr = t >> 4;
    float a0 = 0.f, a1 = 0.f, a2 = 0.f, a3 = 0.f;
#pragma unroll 8
    for (int k = 0; k < 256; k += 4) {
        a0 = fmaf(Xs[lr][k + 0], W[(size_t)(k + 0) * DD + col], a0);
        a1 = fmaf(Xs[lr][k + 1], W[(size_t)(k + 1) * DD + col], a1);
        a2 = fmaf(Xs[lr][k + 2], W[(size_t)(k + 2) * DD + col], a2);
        a3 = fmaf(Xs[lr][k + 3], W[(size_t)(k + 3) * DD + col], a3);
    }
    O[(size_t)(r0 + lr) * DD + col] = (a0 + a1) + (a2 + a3);
}

// ------ tensor-core flash attention v5: K single plane, 2-stage pipeline ----
#define STAGE_BYTES 32768
#define ATT_SMEM 74688

__global__ void __launch_bounds__(256) attn_tc4(
    const float* __restrict__ hq,
    const __half* __restrict__ Kh, const __half* __restrict__ Vh,
    const int* __restrict__ mask, int klen, int kps) {
    extern __shared__ char sm[];
    float* Sst = (float*)(sm + 65536);
    float* rowM = (float*)(sm + 73984);
    float* rowL = (float*)(sm + 74048);
    float* rowS = (float*)(sm + 74112);
    int* mk = (int*)(sm + 74176);
    uint32_t uBase = smem_u32(sm);

    int t = threadIdx.x;
    int w = t >> 5, lane = t & 31;
    int g = lane >> 2, tig = lane & 3;
    int q2 = lane >> 3, r8 = lane & 7;
    int split = blockIdx.x, h = blockIdx.y, b = blockIdx.z;
    int key0 = split * kps;
    int ntiles = kps >> 7;

    {
        int r = t >> 4, c4 = (t & 15) << 2;
        *(float4*)&Sst[r * 64 + c4] =
            *(const float4*)(hq + (size_t)(b * QL + r) * DD + h * HD + c4);
    }
    if (t < 16) { rowM[t] = -3e38f; rowL[t] = 0.f; rowS[t] = 0.f; }
    __syncthreads();

#define LOAD_TILE(k0_, stg_) do {                                               \
    _Pragma("unroll")                                                           \
    for (int pl_ = 0; pl_ < 2; pl_++) {                                         \
        const __half* Gp_ = (pl_ == 0) ? Kh : Vh;                               \
        uint32_t sb_ = (stg_) + pl_ * 16384;                                    \
        _Pragma("unroll")                                                       \
        for (int u_ = 0; u_ < 4; u_++) {                                        \
            int f_ = t + 256 * u_;                                              \
            int row_ = f_ >> 3, ch_ = f_ & 7;                                   \
            const char* gp_ = (const char*)(Gp_ +                               \
                ((size_t)b * klen + (k0_) + row_) * DD + h * HD) + ch_ * 16;    \
            uint32_t sa_ = sb_ + row_ * 128 + (((ch_ ^ (row_ & 7))) << 4);      \
            cp_a16(sa_, gp_);                                                   \
        }                                                                       \
    }                                                                           \
} while (0)

    LOAD_TILE(key0, uBase);
    CP_COMMIT();

    uint32_t qh[4][4], ql[4][4];
#pragma unroll
    for (int s = 0; s < 4; s++) {
        int cb = s * 16 + tig * 2;
        split2(Sst[g * 64 + cb], Sst[g * 64 + cb + 1], qh[s][0], ql[s][0]);
        split2(Sst[(g + 8) * 64 + cb], Sst[(g + 8) * 64 + cb + 1], qh[s][1], ql[s][1]);
        split2(Sst[g * 64 + cb + 8], Sst[g * 64 + cb + 9], qh[s][2], ql[s][2]);
        split2(Sst[(g + 8) * 64 + cb + 8], Sst[(g + 8) * 64 + cb + 9], qh[s][3], ql[s][3]);
    }

    float acc[4] = {0.f, 0.f, 0.f, 0.f};
    uint32_t* SW = (uint32_t*)Sst;

    for (int kt = 0; kt < ntiles; kt++) {
        uint32_t stage = uBase + (kt & 1) * STAGE_BYTES;
        int k0 = key0 + (kt << 7);
        __syncthreads();
        if (kt + 1 < ntiles) {
            LOAD_TILE(k0 + 128, uBase + ((kt + 1) & 1) * STAGE_BYTES);
            CP_COMMIT();
            CP_WAIT1();
        } else {
            CP_WAIT0();
        }
        __syncthreads();
        if (t < 128) mk[t] = mask[(size_t)b * klen + k0 + t];

        // ---- QK (2-pass: qh*k + ql*k): warp w covers keys [w*16, w*16+16) --
        float c2[2][4];
#pragma unroll
        for (int j = 0; j < 2; j++)
#pragma unroll
            for (int e = 0; e < 4; e++) c2[j][e] = 0.f;
#pragma unroll
        for (int s = 0; s < 4; s++) {
            int row = w * 16 + (q2 >> 1) * 8 + r8;
            int ch = s * 2 + (q2 & 1);
            uint32_t off = stage + row * 128 + ((ch ^ (row & 7)) << 4);
            uint32_t rh[4];
            ldm_x4(rh, off);
            uint32_t b0h[2] = {rh[0], rh[1]}, b1h[2] = {rh[2], rh[3]};
            mma16(c2[0], qh[s], b0h); mma16(c2[0], ql[s], b0h);
            mma16(c2[1], qh[s], b1h); mma16(c2[1], ql[s], b1h);
        }
#pragma unroll
        for (int j = 0; j < 2; j++) {
            int kc = w * 16 + j * 8 + tig * 2;
            Sst[g * SSTR + kc] = c2[j][0] * 0.125f;
            Sst[g * SSTR + kc + 1] = c2[j][1] * 0.125f;
            Sst[(g + 8) * SSTR + kc] = c2[j][2] * 0.125f;
            Sst[(g + 8) * SSTR + kc + 1] = c2[j][3] * 0.125f;
        }
        __syncthreads();

        // ---- online softmax; pack P hi/lo pairs in-place ----
        {
            int row = t >> 4, sub = t & 15;
            int cb = sub * 8;
            float sv[8];
#pragma unroll
            for (int i = 0; i < 8; i++) sv[i] = Sst[row * SSTR + cb + i];
            float lmax = -3e38f;
#pragma unroll
            for (int i = 0; i < 8; i++)
                if (mk[cb + i]) lmax = fmaxf(lmax, sv[i]);
#pragma unroll
            for (int o = 8; o; o >>= 1) lmax = fmaxf(lmax, __shfl_xor_sync(~0u, lmax, o));
            float oldm = rowM[row];
            float newm = fmaxf(oldm, lmax);
            float pv[8];
            float lsum = 0.f;
#pragma unroll
            for (int i = 0; i < 8; i++) {
                pv[i] = mk[cb + i] ? fexp(sv[i] - newm) : 0.f;
                lsum += pv[i];
            }
#pragma unroll
            for (int o = 8; o; o >>= 1) lsum += __shfl_xor_sync(~0u, lsum, o);
            if (sub == 0) {
                float sc = fexp(oldm - newm);
                rowS[row] = sc;
                rowL[row] = rowL[row] * sc + lsum;
                rowM[row] = newm;
            }
#pragma unroll
            for (int i = 0; i < 8; i += 2) {
                uint32_t hi, lo;
                split2(pv[i], pv[i + 1], hi, lo);
                SW[row * SSTR + cb + i] = hi;
                SW[row * SSTR + cb + i + 1] = lo;
            }
        }
        __syncthreads();

        // ---- PV (2-pass): warp w covers dims [w*8, w*8+8) ----
        {
            float s0 = rowS[g], s1 = rowS[g + 8];
            acc[0] *= s0; acc[1] *= s0; acc[2] *= s1; acc[3] *= s1;
#pragma unroll
            for (int kb = 0; kb < 4; kb++) {
                int vrow = kb * 32 + q2 * 8 + r8;
                uint32_t voff = stage + 16384 + vrow * 128 + ((w ^ (vrow & 7)) << 4);
                uint32_t v4[4];
                ldm_x4_t(v4, voff);
#pragma unroll
                for (int kh2 = 0; kh2 < 2; kh2++) {
                    int kk = kb * 32 + kh2 * 16;
                    uint32_t ah[4] = {SW[g * SSTR + kk + tig * 2],
                                      SW[(g + 8) * SSTR + kk + tig * 2],
                                      SW[g * SSTR + kk + 8 + tig * 2],
                                      SW[(g + 8) * SSTR + kk + 8 + tig * 2]};
                    uint32_t al[4] = {SW[g * SSTR + kk + tig * 2 + 1],
                                      SW[(g + 8) * SSTR + kk + tig * 2 + 1],
                                      SW[g * SSTR + kk + 8 + tig * 2 + 1],
                                      SW[(g + 8) * SSTR + kk + 8 + tig * 2 + 1]};
                    uint32_t bh[2] = {v4[2 * kh2], v4[2 * kh2 + 1]};
                    mma16(acc, ah, bh);
                    mma16(acc, al, bh);
                }
            }
        }
    }
    size_t pbase = ((size_t)(b * NH + h) * MAXS + split) * QL;
    float* pa = g_pacc + pbase * HD;
    int cc = w * 8 + tig * 2;
    *(float2*)(pa + (size_t)g * HD + cc) = make_float2(acc[0], acc[1]);
    *(float2*)(pa + (size_t)(g + 8) * HD + cc) = make_float2(acc[2], acc[3]);
    if (t < 16) { g_pm[pbase + t] = rowM[t]; g_pl[pbase + t] = rowL[t]; }
}

// ------------------------- merge split-K partials ---------------------------
__global__ void __launch_bounds__(256) attn_merge(float* __restrict__ vec, int nsplit) {
    __shared__ float w[MAXS][16];
    __shared__ float invL[16];
    int t = threadIdx.x;
    int h = blockIdx.x, b = blockIdx.y;
    size_t base = (size_t)(b * NH + h) * MAXS * QL;
    if (t < 16) {
        float M = -3e38f;
        for (int s = 0; s < nsplit; s++) M = fmaxf(M, g_pm[base + s * QL + t]);
        float L = 0.f;
        for (int s = 0; s < nsplit; s++) {
            float ww = fexp(g_pm[base + s * QL + t] - M);
            w[s][t] = ww;
            L += g_pl[base + s * QL + t] * ww;
        }
        invL[t] = 1.f / L;
    }
    __syncthreads();
    int r = t >> 4, c4 = (t & 15) << 2;
    float ox = 0.f, oy = 0.f, oz = 0.f, ow = 0.f;
    for (int s = 0; s < nsplit; s++) {
        float ww = w[s][r];
        float4 a = *(const float4*)(g_pacc + (base + s * QL + r) * HD + c4);
        ox = fmaf(a.x, ww, ox); oy = fmaf(a.y, ww, oy);
        oz = fmaf(a.z, ww, oz); ow = fmaf(a.w, ww, ow);
    }
    float il = invL[r];
    *(float4*)(vec + (size_t)(b * QL + r) * DD + h * HD + c4) =
        make_float4(ox * il, oy * il, oz * il, ow * il);
}

// ------------------------- gate + residual ----------------------------------
__global__ void __launch_bounds__(256) gate_kernel(
    const float* __restrict__ mem, const float* __restrict__ ao,
    const float* __restrict__ Wg, const float* __restrict__ bg,
    float* __restrict__ out) {
    __shared__ float xs[512];
    int row = blockIdx.x;
    int c = threadIdx.x;
    xs[c] = mem[(size_t)row * DD + c];
    xs[256 + c] = ao[(size_t)row * DD + c];
    __syncthreads();
    float s0 = 0.f, s1 = 0.f, s2 = 0.f, s3 = 0.f;
#pragma unroll 4
    for (int k = 0; k < 512; k += 4) {
        float4 x = *(float4*)&xs[k];
        s0 = fmaf(x.x, Wg[(size_t)(k + 0) * DD + c], s0);
        s1 = fmaf(x.y, Wg[(size_t)(k + 1) * DD + c], s1);
        s2 = fmaf(x.z, Wg[(size_t)(k + 2) * DD + c], s2);
        s3 = fmaf(x.w, Wg[(size_t)(k + 3) * DD + c], s3);
    }
    float sum = (s0 + s1) + (s2 + s3) + bg[c];
    float gate = 1.f / (1.f + fexp(-sum));
    out[(size_t)row * DD + c] = gate * xs[c] + (1.f - gate) * xs[256 + c];
}

// ------------------------- launch -------------------------------------------
extern "C" void kernel_launch(void* const* d_in, const int* in_sizes, int n_in,
                              void* d_out, int out_size) {
    const float* pattern = (const float*)d_in[0];
    const float* graph = (const float*)d_in[1];
    const int* pmask = (const int*)d_in[2];
    const int* gmask = (const int*)d_in[3];
    const float* pW[6];
    const float* gW[6];
    for (int i = 0; i < 6; i++) pW[i] = (const float*)d_in[4 + i];
    for (int i = 0; i < 6; i++) gW[i] = (const float*)d_in[10 + i];
    float* out = (float*)d_out;

    float *memb, *hq, *vec, *ao;
    __half *khg, *vhg, *khp, *vhp, *wh;
    cudaGetSymbolAddress((void**)&memb, g_mem);
    cudaGetSymbolAddress((void**)&hq, g_hq);
    cudaGetSymbolAddress((void**)&vec, g_vec);
    cudaGetSymbolAddress((void**)&ao, g_ao);
    cudaGetSymbolAddress((void**)&khg, g_kh_g);
    cudaGetSymbolAddress((void**)&vhg, g_vh_g);
    cudaGetSymbolAddress((void**)&khp, g_kh_p);
    cudaGetSymbolAddress((void**)&vhp, g_vh_p);
    cudaGetSymbolAddress((void**)&wh, g_wkv_h);
    float* mem0 = memb;
    float* mem1 = memb + BB * QL * DD;

    cudaFuncSetAttribute(attn_tc4, cudaFuncAttributeMaxDynamicSharedMemorySize,
                         ATT_SMEM);
    cudaFuncSetAttribute(gemm_kv, cudaFuncAttributeMaxDynamicSharedMemorySize,
                         KV_SMEM);

    // 4th launch gets profiled -> graph gemm_kv
    pool_kernel<<<256, 256>>>(graph, mem0);                               // 1
    split_wkv<<<512, 256>>>(gW[1], gW[2], wh + 512 * DD);                 // 2
    split_wkv<<<512, 256>>>(pW[1], pW[2], wh);                            // 3
    gemm_kv<<<GM / 128, 256, KV_SMEM>>>(graph, wh + 512 * DD, khg, vhg);  // 4
    gemm_kv<<<PM / 128, 256, KV_SMEM>>>(pattern, wh, khp, vhp);           // 5

    float* cur = mem0;
    float* other = mem1;
    for (int it = 0; it < 3; it++) {
        for (int ph = 0; ph < 2; ph++) {
            const float* const* W = ph ? gW : pW;
            const __half* kh = ph ? khg : khp;
            const __half* vh = ph ? vhg : vhp;
            const int* mask = ph ? gmask : pmask;
            int klen = ph ? GLEN : PLEN;
            int splits = ph ? 16 : 4;
            int kps = klen / splits;

            gemm_small<<<dim3(16, 16), 256>>>(cur, W[0], hq);
            attn_tc4<<<dim3(splits, NH, BB), 256, ATT_SMEM>>>(hq, kh, vh,
                                                              mask, klen, kps);
            attn_merge<<<dim3(NH, BB), 256>>>(vec, splits);
            gemm_small<<<dim3(16, 16), 256>>>(vec, W[3], ao);

            bool last = (it == 2 && ph == 1);
            float* dst = last ? out : other;
            gate_kernel<<<256, 256>>>(cur, ao, W[4], W[5], dst);
            other = cur;
            cur = dst;
        }
    }
}

// round 12
// speedup vs baseline: 1.4527x; 1.0635x over previous
#include <cuda_runtime.h>
#include <cuda_fp16.h>
#include <cstdint>

#define BB 16
#define QL 16
#define DD 256
#define NH 4
#define HD 64
#define PLEN 512
#define GLEN 16384
#define MAXS 32
#define GM (BB * GLEN)      // 262144
#define PM (BB * PLEN)      // 8192
#define SSTR 132

// ------------------------- scratch (device globals) -------------------------
__device__ __half g_kh_g[(size_t)GM * DD];
__device__ __half g_vh_g[(size_t)GM * DD];
__device__ __half g_kh_p[PM * DD];
__device__ __half g_vh_p[PM * DD];
__device__ __half g_wkv_h[2][512 * DD];
__device__ float g_mem[2][BB * QL * DD];
__device__ float g_hq[BB * QL * DD];
__device__ float g_vec[BB * QL * DD];
__device__ float g_ao[BB * QL * DD];
__device__ float g_pacc[BB * NH * MAXS * QL * HD];
__device__ float g_pm[BB * NH * MAXS * QL];
__device__ float g_pl[BB * NH * MAXS * QL];

// ------------------------- fast exp on FMA pipe -----------------------------
__device__ __forceinline__ float fexp(float x) {
    float y = x * 1.4426950408889634f;
    y = fmaxf(y, -125.0f);
    float n = rintf(y);
    float f = y - n;
    float p = 1.3333558146e-3f;
    p = fmaf(p, f, 9.6181291076e-3f);
    p = fmaf(p, f, 5.5504108664e-2f);
    p = fmaf(p, f, 2.4022650696e-1f);
    p = fmaf(p, f, 6.9314718056e-1f);
    p = fmaf(p, f, 1.0f);
    return __int_as_float(((int)n + 127) << 23) * p;
}

// ------------------------- mma / smem / cp.async helpers --------------------
__device__ __forceinline__ uint32_t smem_u32(const void* p) {
    uint32_t a;
    asm("{ .reg .u64 t; cvta.to.shared.u64 t, %1; cvt.u32.u64 %0, t; }" : "=r"(a) : "l"(p));
    return a;
}
__device__ __forceinline__ void ldm_x4(uint32_t* r, uint32_t addr) {
    asm volatile("ldmatrix.sync.aligned.m8n8.x4.shared.b16 {%0,%1,%2,%3}, [%4];"
                 : "=r"(r[0]), "=r"(r[1]), "=r"(r[2]), "=r"(r[3]) : "r"(addr));
}
__device__ __forceinline__ void ldm_x4_t(uint32_t* r, uint32_t addr) {
    asm volatile("ldmatrix.sync.aligned.m8n8.x4.trans.shared.b16 {%0,%1,%2,%3}, [%4];"
                 : "=r"(r[0]), "=r"(r[1]), "=r"(r[2]), "=r"(r[3]) : "r"(addr));
}
__device__ __forceinline__ void mma16(float* c, const uint32_t* a, const uint32_t* b) {
    asm volatile(
        "mma.sync.aligned.m16n8k16.row.col.f32.f16.f16.f32 "
        "{%0,%1,%2,%3}, {%4,%5,%6,%7}, {%8,%9}, {%0,%1,%2,%3};"
        : "+f"(c[0]), "+f"(c[1]), "+f"(c[2]), "+f"(c[3])
        : "r"(a[0]), "r"(a[1]), "r"(a[2]), "r"(a[3]), "r"(b[0]), "r"(b[1]));
}
__device__ __forceinline__ void cp_a16(uint32_t s, const void* g) {
    asm volatile("cp.async.cg.shared.global [%0], [%1], 16;" :: "r"(s), "l"(g));
}
#define CP_COMMIT() asm volatile("cp.async.commit_group;" ::: "memory")
#define CP_WAIT0()  asm volatile("cp.async.wait_group 0;" ::: "memory")
#define CP_WAIT1()  asm volatile("cp.async.wait_group 1;" ::: "memory")

__device__ __forceinline__ uint32_t packh2(float a, float b) {
    __half2 h = __floats2half2_rn(a, b);
    return *(uint32_t*)&h;
}

// ------------------------- weight convert (transposed, concat K|V) ----------
__global__ void __launch_bounds__(256) split_wkv(const float* __restrict__ Wk,
                                                 const float* __restrict__ Wv,
                                                 __half* __restrict__ Th) {
    int n = blockIdx.x, k = threadIdx.x;
    const float* W = (n < 256) ? Wk : Wv;
    Th[(size_t)n * DD + k] = __float2half_rn(W[(size_t)k * DD + (n & 255)]);
}

// ------- mma GEMM v4: A-panel resident, N-loop in block, cp.async B ---------
#define A_BYTES 65536
#define BSTG 10240
#define KV_SMEM (A_BYTES + 2 * BSTG)   // 86016

__global__ void __launch_bounds__(256) gemm_kv(
    const float* __restrict__ X, const __half* __restrict__ Bhp,
    __half* __restrict__ Kh, __half* __restrict__ Vh) {
    extern __shared__ char smk[];
    uint32_t uA = smem_u32(smk);
    uint32_t uB = uA + A_BYTES;

    int t = threadIdx.x;
    int wid = t >> 5, lane = t & 31;
    int wm = (wid & 3) * 32;
    int wn = (wid >> 2) * 64;
    size_t m0 = (size_t)blockIdx.x * 128;
    int q = lane >> 3, r8 = lane & 7;

    // ---- load & convert full A panel (fp32 -> fp16, XOR-swizzled rows) ----
#pragma unroll 8
    for (int u = 0; u < 32; u++) {
        int f = t + 256 * u;
        int row = f >> 6, c = f & 63;
        float4 v = *(const float4*)(X + (m0 + row) * DD + c * 4);
        uint32_t off = row * 512 + (((c >> 1) ^ (row & 7)) << 4) + (c & 1) * 8;
        *(uint2*)(smk + off) = make_uint2(packh2(v.x, v.y), packh2(v.z, v.w));
    }
    __syncthreads();

    for (int nb = 0; nb < 4; nb++) {
        int n0 = nb * 128;
        float acc[2][8][4];
#pragma unroll
        for (int i = 0; i < 2; i++)
#pragma unroll
            for (int j = 0; j < 8; j++)
#pragma unroll
                for (int e = 0; e < 4; e++) acc[i][j][e] = 0.f;

#pragma unroll
        for (int u = 0; u < 2; u++) {
            int f = t + 256 * u;
            int row = f >> 2, c = f & 3;
            cp_a16(uB + row * 80 + c * 16, Bhp + (size_t)(n0 + row) * DD + c * 8);
        }
        CP_COMMIT();

        for (int c = 0; c < 8; c++) {
            uint32_t curB = uB + (c & 1) * BSTG;
            __syncthreads();
            if (c + 1 < 8) {
                int k0n = (c + 1) * 32;
                uint32_t nxtB = uB + ((c + 1) & 1) * BSTG;
#pragma unroll
                for (int u = 0; u < 2; u++) {
                    int f = t + 256 * u;
                    int row = f >> 2, cc = f & 3;
                    cp_a16(nxtB + row * 80 + cc * 16,
                           Bhp + (size_t)(n0 + row) * DD + k0n + cc * 8);
                }
                CP_COMMIT();
                CP_WAIT1();
            } else {
                CP_WAIT0();
            }
            __syncthreads();

            int k0 = c * 32;
#pragma unroll
            for (int s = 0; s < 2; s++) {
                int kk = k0 + s * 16;
                uint32_t aH[2][4], bH[8][2];
#pragma unroll
                for (int i = 0; i < 2; i++) {
                    int row = wm + i * 16 + (q & 1) * 8 + r8;
                    int col = kk + (q >> 1) * 8;
                    uint32_t off = row * 512 + ((((uint32_t)col >> 3) ^ (row & 7)) << 4);
                    ldm_x4(aH[i], uA + off);
                }
#pragma unroll
                for (int p = 0; p < 4; p++) {
                    int n = wn + p * 16 + (q >> 1) * 8 + r8;
                    int col = s * 16 + (q & 1) * 8;
                    uint32_t rh[4];
                    ldm_x4(rh, curB + (uint32_t)(n * 40 + col) * 2);
                    bH[2 * p][0] = rh[0]; bH[2 * p][1] = rh[1];
                    bH[2 * p + 1][0] = rh[2]; bH[2 * p + 1][1] = rh[3];
                }
#pragma unroll
                for (int i = 0; i < 2; i++)
#pragma unroll
                    for (int j = 0; j < 8; j++)
                        mma16(acc[i][j], aH[i], bH[j]);
            }
        }

        __half* Dst = (n0 < 256) ? Kh : Vh;
        int cbase = n0 & 255;
#pragma unroll
        for (int i = 0; i < 2; i++) {
            int r0 = wm + i * 16 + (lane >> 2);
#pragma unroll
            for (int j = 0; j < 8; j++) {
                int cc = cbase + wn + j * 8 + (lane & 3) * 2;
                *(uint32_t*)(Dst + (m0 + r0) * DD + cc) = packh2(acc[i][j][0], acc[i][j][1]);
                *(uint32_t*)(Dst + (m0 + r0 + 8) * DD + cc) = packh2(acc[i][j][2], acc[i][j][3]);
            }
        }
    }
}

// ------------------------- mean pooling: graph -> mem0 ----------------------
__global__ void __launch_bounds__(256) pool_kernel(const float* __restrict__ graph,
                                                   float* __restrict__ mem0) {
    int bm = blockIdx.x;
    int d = threadIdx.x;
    const float* src = graph + (size_t)bm * 1024 * DD + d;
    float s0 = 0.f, s1 = 0.f, s2 = 0.f, s3 = 0.f;
    for (int r = 0; r < 1024; r += 4) {
        s0 += src[(size_t)(r + 0) * DD];
        s1 += src[(size_t)(r + 1) * DD];
        s2 += src[(size_t)(r + 2) * DD];
        s3 += src[(size_t)(r + 3) * DD];
    }
    mem0[(size_t)bm * DD + d] = (s0 + s1 + s2 + s3) * (1.0f / 1024.0f);
}

// ---------------- small GEMM: O[256,256] = X @ W, grid (16,16) --------------
__global__ void __launch_bounds__(256) gemm_small(const float* __restrict__ X,
                                                  const float* __restrict__ W,
                                                  float* __restrict__ O) {
    __shared__ float Xs[16][256];
    int t = threadIdx.x;
    int r0 = blockIdx.y * 16, n0 = blockIdx.x * 16;
#pragma unroll
    for (int u = 0; u < 4; u++) {
        int f = t + 256 * u;
        int row = f >> 6, c4 = (f & 63) << 2;
        *(float4*)&Xs[row][c4] = *(const float4*)(X + (size_t)(r0 + row) * DD + c4);
    }
    __syncthreads();
    int col = n0 + (t & 15), lr = t >> 4;
    float a0 = 0.f, a1 = 0.f, a2 = 0.f, a3 = 0.f;
#pragma unroll 8
    for (int k = 0; k < 256; k += 4) {
        a0 = fmaf(Xs[lr][k + 0], W[(size_t)(k + 0) * DD + col], a0);
        a1 = fmaf(Xs[lr][k + 1], W[(size_t)(k + 1) * DD + col], a1);
        a2 = fmaf(Xs[lr][k + 2], W[(size_t)(k + 2) * DD + col], a2);
        a3 = fmaf(Xs[lr][k + 3], W[(size_t)(k + 3) * DD + col], a3);
    }
    O[(size_t)(r0 + lr) * DD + col] = (a0 + a1) + (a2 + a3);
}

// ------ flash attention v6: single-plane Q/K/V/P, cp.async 2-stage ----------
#define STAGE_BYTES 32768
#define ATT_SMEM 74688

__global__ void __launch_bounds__(256) attn_tc4(
    const float* __restrict__ hq,
    const __half* __restrict__ Kh, const __half* __restrict__ Vh,
    const int* __restrict__ mask, int klen, int kps) {
    extern __shared__ char sm[];
    float* Sst = (float*)(sm + 65536);
    float* rowM = (float*)(sm + 73984);
    float* rowL = (float*)(sm + 74048);
    float* rowS = (float*)(sm + 74112);
    int* mk = (int*)(sm + 74176);
    uint32_t uBase = smem_u32(sm);

    int t = threadIdx.x;
    int w = t >> 5, lane = t & 31;
    int g = lane >> 2, tig = lane & 3;
    int q2 = lane >> 3, r8 = lane & 7;
    int split = blockIdx.x, h = blockIdx.y, b = blockIdx.z;
    int key0 = split * kps;
    int ntiles = kps >> 7;

    {
        int r = t >> 4, c4 = (t & 15) << 2;
        *(float4*)&Sst[r * 64 + c4] =
            *(const float4*)(hq + (size_t)(b * QL + r) * DD + h * HD + c4);
    }
    if (t < 16) { rowM[t] = -3e38f; rowL[t] = 0.f; rowS[t] = 0.f; }
    __syncthreads();

#define LOAD_TILE(k0_, stg_) do {                                               \
    _Pragma("unroll")                                                           \
    for (int pl_ = 0; pl_ < 2; pl_++) {                                         \
        const __half* Gp_ = (pl_ == 0) ? Kh : Vh;                               \
        uint32_t sb_ = (stg_) + pl_ * 16384;                                    \
        _Pragma("unroll")                                                       \
        for (int u_ = 0; u_ < 4; u_++) {                                        \
            int f_ = t + 256 * u_;                                              \
            int row_ = f_ >> 3, ch_ = f_ & 7;                                   \
            const char* gp_ = (const char*)(Gp_ +                               \
                ((size_t)b * klen + (k0_) + row_) * DD + h * HD) + ch_ * 16;    \
            uint32_t sa_ = sb_ + row_ * 128 + (((ch_ ^ (row_ & 7))) << 4);      \
            cp_a16(sa_, gp_);                                                   \
        }                                                                       \
    }                                                                           \
} while (0)

    LOAD_TILE(key0, uBase);
    CP_COMMIT();

    // Q fragments: single fp16 plane
    uint32_t qh[4][4];
#pragma unroll
    for (int s = 0; s < 4; s++) {
        int cb = s * 16 + tig * 2;
        qh[s][0] = packh2(Sst[g * 64 + cb], Sst[g * 64 + cb + 1]);
        qh[s][1] = packh2(Sst[(g + 8) * 64 + cb], Sst[(g + 8) * 64 + cb + 1]);
        qh[s][2] = packh2(Sst[g * 64 + cb + 8], Sst[g * 64 + cb + 9]);
        qh[s][3] = packh2(Sst[(g + 8) * 64 + cb + 8], Sst[(g + 8) * 64 + cb + 9]);
    }

    float acc[4] = {0.f, 0.f, 0.f, 0.f};
    uint32_t* SW = (uint32_t*)Sst;

    for (int kt = 0; kt < ntiles; kt++) {
        uint32_t stage = uBase + (kt & 1) * STAGE_BYTES;
        int k0 = key0 + (kt << 7);
        __syncthreads();
        if (kt + 1 < ntiles) {
            LOAD_TILE(k0 + 128, uBase + ((kt + 1) & 1) * STAGE_BYTES);
            CP_COMMIT();
            CP_WAIT1();
        } else {
            CP_WAIT0();
        }
        __syncthreads();
        if (t < 128) mk[t] = mask[(size_t)b * klen + k0 + t];

        // ---- QK (1-pass): warp w covers keys [w*16, w*16+16) ----
        float c2[2][4];
#pragma unroll
        for (int j = 0; j < 2; j++)
#pragma unroll
            for (int e = 0; e < 4; e++) c2[j][e] = 0.f;
#pragma unroll
        for (int s = 0; s < 4; s++) {
            int row = w * 16 + (q2 >> 1) * 8 + r8;
            int ch = s * 2 + (q2 & 1);
            uint32_t off = stage + row * 128 + ((ch ^ (row & 7)) << 4);
            uint32_t rh[4];
            ldm_x4(rh, off);
            uint32_t b0h[2] = {rh[0], rh[1]}, b1h[2] = {rh[2], rh[3]};
            mma16(c2[0], qh[s], b0h);
            mma16(c2[1], qh[s], b1h);
        }
#pragma unroll
        for (int j = 0; j < 2; j++) {
            int kc = w * 16 + j * 8 + tig * 2;
            Sst[g * SSTR + kc] = c2[j][0] * 0.125f;
            Sst[g * SSTR + kc + 1] = c2[j][1] * 0.125f;
            Sst[(g + 8) * SSTR + kc] = c2[j][2] * 0.125f;
            Sst[(g + 8) * SSTR + kc + 1] = c2[j][3] * 0.125f;
        }
        __syncthreads();

        // ---- online softmax; pack P fp16 pairs (even words) ----
        {
            int row = t >> 4, sub = t & 15;
            int cb = sub * 8;
            float sv[8];
#pragma unroll
            for (int i = 0; i < 8; i++) sv[i] = Sst[row * SSTR + cb + i];
            float lmax = -3e38f;
#pragma unroll
            for (int i = 0; i < 8; i++)
                if (mk[cb + i]) lmax = fmaxf(lmax, sv[i]);
#pragma unroll
            for (int o = 8; o; o >>= 1) lmax = fmaxf(lmax, __shfl_xor_sync(~0u, lmax, o));
            float oldm = rowM[row];
            float newm = fmaxf(oldm, lmax);
            float pv[8];
            float lsum = 0.f;
#pragma unroll
            for (int i = 0; i < 8; i++) {
                pv[i] = mk[cb + i] ? fexp(sv[i] - newm) : 0.f;
                lsum += pv[i];
            }
#pragma unroll
            for (int o = 8; o; o >>= 1) lsum += __shfl_xor_sync(~0u, lsum, o);
            if (sub == 0) {
                float sc = fexp(oldm - newm);
                rowS[row] = sc;
                rowL[row] = rowL[row] * sc + lsum;
                rowM[row] = newm;
            }
#pragma unroll
            for (int i = 0; i < 8; i += 2)
                SW[row * SSTR + cb + i] = packh2(pv[i], pv[i + 1]);
        }
        __syncthreads();

        // ---- PV (1-pass): warp w covers dims [w*8, w*8+8) ----
        {
            float s0 = rowS[g], s1 = rowS[g + 8];
            acc[0] *= s0; acc[1] *= s0; acc[2] *= s1; acc[3] *= s1;
#pragma unroll
            for (int kb = 0; kb < 4; kb++) {
                int vrow = kb * 32 + q2 * 8 + r8;
                uint32_t voff = stage + 16384 + vrow * 128 + ((w ^ (vrow & 7)) << 4);
                uint32_t v4[4];
                ldm_x4_t(v4, voff);
#pragma unroll
                for (int kh2 = 0; kh2 < 2; kh2++) {
                    int kk = kb * 32 + kh2 * 16;
                    uint32_t ah[4] = {SW[g * SSTR + kk + tig * 2],
                                      SW[(g + 8) * SSTR + kk + tig * 2],
                                      SW[g * SSTR + kk + 8 + tig * 2],
                                      SW[(g + 8) * SSTR + kk + 8 + tig * 2]};
                    uint32_t bh[2] = {v4[2 * kh2], v4[2 * kh2 + 1]};
                    mma16(acc, ah, bh);
                }
            }
        }
    }
    size_t pbase = ((size_t)(b * NH + h) * MAXS + split) * QL;
    float* pa = g_pacc + pbase * HD;
    int cc = w * 8 + tig * 2;
    *(float2*)(pa + (size_t)g * HD + cc) = make_float2(acc[0], acc[1]);
    *(float2*)(pa + (size_t)(g + 8) * HD + cc) = make_float2(acc[2], acc[3]);
    if (t < 16) { g_pm[pbase + t] = rowM[t]; g_pl[pbase + t] = rowL[t]; }
}

// ------------------------- merge split-K partials ---------------------------
__global__ void __launch_bounds__(256) attn_merge(float* __restrict__ vec, int nsplit) {
    __shared__ float w[MAXS][16];
    __shared__ float invL[16];
    int t = threadIdx.x;
    int h = blockIdx.x, b = blockIdx.y;
    size_t base = (size_t)(b * NH + h) * MAXS * QL;
    if (t < 16) {
        float M = -3e38f;
        for (int s = 0; s < nsplit; s++) M = fmaxf(M, g_pm[base + s * QL + t]);
        float L = 0.f;
        for (int s = 0; s < nsplit; s++) {
            float ww = fexp(g_pm[base + s * QL + t] - M);
            w[s][t] = ww;
            L += g_pl[base + s * QL + t] * ww;
        }
        invL[t] = 1.f / L;
    }
    __syncthreads();
    int r = t >> 4, c4 = (t & 15) << 2;
    float ox = 0.f, oy = 0.f, oz = 0.f, ow = 0.f;
    for (int s = 0; s < nsplit; s++) {
        float ww = w[s][r];
        float4 a = *(const float4*)(g_pacc + (base + s * QL + r) * HD + c4);
        ox = fmaf(a.x, ww, ox); oy = fmaf(a.y, ww, oy);
        oz = fmaf(a.z, ww, oz); ow = fmaf(a.w, ww, ow);
    }
    float il = invL[r];
    *(float4*)(vec + (size_t)(b * QL + r) * DD + h * HD + c4) =
        make_float4(ox * il, oy * il, oz * il, ow * il);
}

// ------------------------- gate + residual ----------------------------------
__global__ void __launch_bounds__(256) gate_kernel(
    const float* __restrict__ mem, const float* __restrict__ ao,
    const float* __restrict__ Wg, const float* __restrict__ bg,
    float* __restrict__ out) {
    __shared__ float xs[512];
    int row = blockIdx.x;
    int c = threadIdx.x;
    xs[c] = mem[(size_t)row * DD + c];
    xs[256 + c] = ao[(size_t)row * DD + c];
    __syncthreads();
    float s0 = 0.f, s1 = 0.f, s2 = 0.f, s3 = 0.f;
#pragma unroll 4
    for (int k = 0; k < 512; k += 4) {
        float4 x = *(float4*)&xs[k];
        s0 = fmaf(x.x, Wg[(size_t)(k + 0) * DD + c], s0);
        s1 = fmaf(x.y, Wg[(size_t)(k + 1) * DD + c], s1);
        s2 = fmaf(x.z, Wg[(size_t)(k + 2) * DD + c], s2);
        s3 = fmaf(x.w, Wg[(size_t)(k + 3) * DD + c], s3);
    }
    float sum = (s0 + s1) + (s2 + s3) + bg[c];
    float gate = 1.f / (1.f + fexp(-sum));
    out[(size_t)row * DD + c] = gate * xs[c] + (1.f - gate) * xs[256 + c];
}

// ------------------------- launch -------------------------------------------
extern "C" void kernel_launch(void* const* d_in, const int* in_sizes, int n_in,
                              void* d_out, int out_size) {
    const float* pattern = (const float*)d_in[0];
    const float* graph = (const float*)d_in[1];
    const int* pmask = (const int*)d_in[2];
    const int* gmask = (const int*)d_in[3];
    const float* pW[6];
    const float* gW[6];
    for (int i = 0; i < 6; i++) pW[i] = (const float*)d_in[4 + i];
    for (int i = 0; i < 6; i++) gW[i] = (const float*)d_in[10 + i];
    float* out = (float*)d_out;

    float *memb, *hq, *vec, *ao;
    __half *khg, *vhg, *khp, *vhp, *wh;
    cudaGetSymbolAddress((void**)&memb, g_mem);
    cudaGetSymbolAddress((void**)&hq, g_hq);
    cudaGetSymbolAddress((void**)&vec, g_vec);
    cudaGetSymbolAddress((void**)&ao, g_ao);
    cudaGetSymbolAddress((void**)&khg, g_kh_g);
    cudaGetSymbolAddress((void**)&vhg, g_vh_g);
    cudaGetSymbolAddress((void**)&khp, g_kh_p);
    cudaGetSymbolAddress((void**)&vhp, g_vh_p);
    cudaGetSymbolAddress((void**)&wh, g_wkv_h);
    float* mem0 = memb;
    float* mem1 = memb + BB * QL * DD;

    cudaFuncSetAttribute(attn_tc4, cudaFuncAttributeMaxDynamicSharedMemorySize,
                         ATT_SMEM);
    cudaFuncSetAttribute(gemm_kv, cudaFuncAttributeMaxDynamicSharedMemorySize,
                         KV_SMEM);

    pool_kernel<<<256, 256>>>(graph, mem0);                               // 1
    split_wkv<<<512, 256>>>(gW[1], gW[2], wh + 512 * DD);                 // 2
    split_wkv<<<512, 256>>>(pW[1], pW[2], wh);                            // 3
    gemm_kv<<<GM / 128, 256, KV_SMEM>>>(graph, wh + 512 * DD, khg, vhg);  // 4 (profiled)
    gemm_kv<<<PM / 128, 256, KV_SMEM>>>(pattern, wh, khp, vhp);           // 5

    float* cur = mem0;
    float* other = mem1;
    for (int it = 0; it < 3; it++) {
        for (int ph = 0; ph < 2; ph++) {
            const float* const* W = ph ? gW : pW;
            const __half* kh = ph ? khg : khp;
            const __half* vh = ph ? vhg : vhp;
            const int* mask = ph ? gmask : pmask;
            int klen = ph ? GLEN : PLEN;
            int splits = ph ? 16 : 4;
            int kps = klen / splits;

            gemm_small<<<dim3(16, 16), 256>>>(cur, W[0], hq);
            attn_tc4<<<dim3(splits, NH, BB), 256, ATT_SMEM>>>(hq, kh, vh,
                                                              mask, klen, kps);
            attn_merge<<<dim3(NH, BB), 256>>>(vec, splits);
            gemm_small<<<dim3(16, 16), 256>>>(vec, W[3], ao);

            bool last = (it == 2 && ph == 1);
            float* dst = last ? out : other;
            gate_kernel<<<256, 256>>>(cur, ao, W[4], W[5], dst);
            other = cur;
            cur = dst;
        }
    }
}